// round 4
// baseline (speedup 1.0000x reference)
#include <cuda_runtime.h>

// ---------------------------------------------------------------------------
// MultiHeadAttention b=2,t=2048,e=512,h=8
// Round 3: TF32 mma.sync, warp tile 64x64 (was 64x32), block tile 128x256.
// Reduces smem bytes/MAC 0.1875 -> 0.125 (kernel was L1-bound at 78%).
// ---------------------------------------------------------------------------

#define NEG_INF (-1e30f)
#define SCALE 0.044194173824159216f   // 1/sqrt(512)
#define SSTR 20                       // smem row stride (words), conflict-free map

static __device__ float g_q[16 * 2048 * 512];
static __device__ float g_k[16 * 2048 * 512];
static __device__ float g_v[16 * 2048 * 512];
static __device__ float g_p[16u * 2048 * 2048];
static __device__ float g_att[16 * 2048 * 512];

__device__ __forceinline__ unsigned f2tf(float x) {
    unsigned r; asm("cvt.rna.tf32.f32 %0, %1;" : "=r"(r) : "f"(x)); return r;
}
__device__ __forceinline__ uint4 f4tf(float4 v) {
    return make_uint4(f2tf(v.x), f2tf(v.y), f2tf(v.z), f2tf(v.w));
}
__device__ __forceinline__ void mma8(float* d, const unsigned* a, const unsigned* b) {
    asm volatile("mma.sync.aligned.m16n8k8.row.col.f32.tf32.tf32.f32 "
                 "{%0,%1,%2,%3}, {%4,%5,%6,%7}, {%8,%9}, {%0,%1,%2,%3};"
                 : "+f"(d[0]), "+f"(d[1]), "+f"(d[2]), "+f"(d[3])
                 : "r"(a[0]), "r"(a[1]), "r"(a[2]), "r"(a[3]),
                   "r"(b[0]), "r"(b[1]));
}

// One 128x256x16 block tile from smem. As: 128 rows (M), Bs: 256 rows (N),
// both [row][k] stride SSTR. Warp (wm 0..1, wn 0..3) computes 64x64.
__device__ __forceinline__ void compute_tile(const unsigned* __restrict__ As,
                                             const unsigned* __restrict__ Bs,
                                             float acc[4][8][4],
                                             int wm, int wn, int g, int tg)
{
#pragma unroll
    for (int kk = 0; kk < 16; kk += 8) {
        unsigned af[4][4];
#pragma unroll
        for (int mi = 0; mi < 4; mi++) {
            const unsigned* p = As + (wm * 64 + mi * 16 + g) * SSTR + kk + tg;
            af[mi][0] = p[0];
            af[mi][1] = p[8 * SSTR];
            af[mi][2] = p[4];
            af[mi][3] = p[8 * SSTR + 4];
        }
        unsigned bf[8][2];
#pragma unroll
        for (int ni = 0; ni < 8; ni++) {
            const unsigned* p = Bs + (wn * 64 + ni * 8 + g) * SSTR + kk + tg;
            bf[ni][0] = p[0];
            bf[ni][1] = p[4];
        }
#pragma unroll
        for (int mi = 0; mi < 4; mi++)
#pragma unroll
            for (int ni = 0; ni < 8; ni++)
                mma8(acc[mi][ni], af[mi], bf[ni]);
    }
}

#define ACC_INIT float acc[4][8][4]; \
    _Pragma("unroll") for (int i = 0; i < 4; i++) \
    _Pragma("unroll") for (int j = 0; j < 8; j++) \
    _Pragma("unroll") for (int k = 0; k < 4; k++) acc[i][j][k] = 0.f;

// ---------------------------------------------------------------------------
// proj: C = X * W^T, M=4096 (tokens), N=4096 (h*e), K=512. out -> (b,h,t,e)
// grid (16, 32)
// ---------------------------------------------------------------------------
__global__ __launch_bounds__(256) void proj_kernel(const float* __restrict__ X,
                                                   const float* __restrict__ W,
                                                   int mode)
{
    __shared__ __align__(16) unsigned As[128 * SSTR];
    __shared__ __align__(16) unsigned Bs[256 * SSTR];
    float* out = (mode == 0) ? g_q : (mode == 1) ? g_k : g_v;

    const int m0 = blockIdx.y * 128, n0 = blockIdx.x * 256;
    const int tid = threadIdx.x;
    const int w = tid >> 5, lane = tid & 31, g = lane >> 2, tg = lane & 3;
    const int wm = w >> 2, wn = w & 3;

    ACC_INIT

    const int arow = tid >> 2, ak4 = (tid & 3) * 4;   // A: rows 0..63 (+64 for it=1)
    float4 pa[2], pb[4];
#pragma unroll
    for (int it = 0; it < 2; it++)
        pa[it] = *(const float4*)(X + (size_t)(m0 + arow + it * 64) * 512 + ak4);
#pragma unroll
    for (int it = 0; it < 4; it++)
        pb[it] = *(const float4*)(W + (size_t)(n0 + arow + it * 64) * 512 + ak4);

    for (int kt = 0; kt < 32; kt++) {
#pragma unroll
        for (int it = 0; it < 2; it++)
            *(uint4*)&As[(arow + it * 64) * SSTR + ak4] = f4tf(pa[it]);
#pragma unroll
        for (int it = 0; it < 4; it++)
            *(uint4*)&Bs[(arow + it * 64) * SSTR + ak4] = f4tf(pb[it]);
        __syncthreads();
        if (kt < 31) {
            int k0 = (kt + 1) * 16;
#pragma unroll
            for (int it = 0; it < 2; it++)
                pa[it] = *(const float4*)(X + (size_t)(m0 + arow + it * 64) * 512 + k0 + ak4);
#pragma unroll
            for (int it = 0; it < 4; it++)
                pb[it] = *(const float4*)(W + (size_t)(n0 + arow + it * 64) * 512 + k0 + ak4);
        }
        compute_tile(As, Bs, acc, wm, wn, g, tg);
        __syncthreads();
    }

#pragma unroll
    for (int mi = 0; mi < 4; mi++)
#pragma unroll
        for (int ni = 0; ni < 8; ni++) {
            int cbase = n0 + wn * 64 + ni * 8 + 2 * tg;
            int h = cbase >> 9, e = cbase & 511;
#pragma unroll
            for (int rr = 0; rr < 2; rr++) {
                int row = m0 + wm * 64 + mi * 16 + g + rr * 8;
                int bb = row >> 11, t = row & 2047;
                float2 v = make_float2(acc[mi][ni][rr * 2], acc[mi][ni][rr * 2 + 1]);
                *(float2*)(out + (((size_t)(bb * 8 + h) * 2048 + t) << 9) + e) = v;
            }
        }
}

// ---------------------------------------------------------------------------
// scores: per z, S = Q K^T * scale + causal. M=N=2048, K=512. grid (8,16,16)
// ---------------------------------------------------------------------------
__global__ __launch_bounds__(256) void scores_kernel()
{
    const int z = blockIdx.z;
    const int m0 = blockIdx.y * 128, n0 = blockIdx.x * 256;
    if (n0 > m0 + 127) return;

    const float* Q = g_q + (size_t)z * 1048576;
    const float* K = g_k + (size_t)z * 1048576;
    float* P = g_p + (size_t)z * 4194304;

    __shared__ __align__(16) unsigned As[128 * SSTR];
    __shared__ __align__(16) unsigned Bs[256 * SSTR];

    const int tid = threadIdx.x;
    const int w = tid >> 5, lane = tid & 31, g = lane >> 2, tg = lane & 3;
    const int wm = w >> 2, wn = w & 3;

    ACC_INIT

    const int arow = tid >> 2, ak4 = (tid & 3) * 4;
    float4 pa[2], pb[4];
#pragma unroll
    for (int it = 0; it < 2; it++)
        pa[it] = *(const float4*)(Q + (size_t)(m0 + arow + it * 64) * 512 + ak4);
#pragma unroll
    for (int it = 0; it < 4; it++)
        pb[it] = *(const float4*)(K + (size_t)(n0 + arow + it * 64) * 512 + ak4);

    for (int kt = 0; kt < 32; kt++) {
#pragma unroll
        for (int it = 0; it < 2; it++)
            *(uint4*)&As[(arow + it * 64) * SSTR + ak4] = f4tf(pa[it]);
#pragma unroll
        for (int it = 0; it < 4; it++)
            *(uint4*)&Bs[(arow + it * 64) * SSTR + ak4] = f4tf(pb[it]);
        __syncthreads();
        if (kt < 31) {
            int k0 = (kt + 1) * 16;
#pragma unroll
            for (int it = 0; it < 2; it++)
                pa[it] = *(const float4*)(Q + (size_t)(m0 + arow + it * 64) * 512 + k0 + ak4);
#pragma unroll
            for (int it = 0; it < 4; it++)
                pb[it] = *(const float4*)(K + (size_t)(n0 + arow + it * 64) * 512 + k0 + ak4);
        }
        compute_tile(As, Bs, acc, wm, wn, g, tg);
        __syncthreads();
    }

#pragma unroll
    for (int mi = 0; mi < 4; mi++)
#pragma unroll
        for (int ni = 0; ni < 8; ni++) {
            int col = n0 + wn * 64 + ni * 8 + 2 * tg;
#pragma unroll
            for (int rr = 0; rr < 2; rr++) {
                int row = m0 + wm * 64 + mi * 16 + g + rr * 8;
                float2 v;
                v.x = (col <= row) ? acc[mi][ni][rr * 2] * SCALE : NEG_INF;
                v.y = (col + 1 <= row) ? acc[mi][ni][rr * 2 + 1] * SCALE : NEG_INF;
                *(float2*)(P + (size_t)row * 2048 + col) = v;
            }
        }
}

// ---------------------------------------------------------------------------
// softmax: one block/row, float4, one read + one write (values in regs).
// ---------------------------------------------------------------------------
__global__ __launch_bounds__(256) void softmax_kernel()
{
    const int row = blockIdx.x;
    const int z = row >> 11;
    const int q = row & 2047;
    float4* P4 = (float4*)(g_p + (size_t)z * 4194304 + (size_t)q * 2048);
    const int end4 = (((q >> 7) + 1) << 7) >> 2;   // multiple of 32, <= 512

    const int tid = threadIdx.x;
    const int lane = tid & 31, wid = tid >> 5;
    __shared__ float red[8];

    float4 vals[2];
    float m = -3.4e38f;
#pragma unroll
    for (int it = 0; it < 2; it++) {
        int c = tid + it * 256;
        if (c < end4) {
            float4 v = P4[c];
            vals[it] = v;
            m = fmaxf(m, fmaxf(fmaxf(v.x, v.y), fmaxf(v.z, v.w)));
        }
    }
#pragma unroll
    for (int s = 16; s > 0; s >>= 1) m = fmaxf(m, __shfl_xor_sync(~0u, m, s));
    if (lane == 0) red[wid] = m;
    __syncthreads();
    m = red[0];
#pragma unroll
    for (int i = 1; i < 8; i++) m = fmaxf(m, red[i]);

    float sum = 0.f;
#pragma unroll
    for (int it = 0; it < 2; it++) {
        int c = tid + it * 256;
        if (c < end4) {
            float4 v = vals[it];
            v.x = expf(v.x - m); v.y = expf(v.y - m);
            v.z = expf(v.z - m); v.w = expf(v.w - m);
            vals[it] = v;
            sum += v.x + v.y + v.z + v.w;
        }
    }
#pragma unroll
    for (int s = 16; s > 0; s >>= 1) sum += __shfl_xor_sync(~0u, sum, s);
    __syncthreads();
    if (lane == 0) red[wid] = sum;
    __syncthreads();
    sum = 0.f;
#pragma unroll
    for (int i = 0; i < 8; i++) sum += red[i];
    const float inv = 1.f / sum;

#pragma unroll
    for (int it = 0; it < 2; it++) {
        int c = tid + it * 256;
        if (c < end4) {
            float4 v = vals[it];
            v.x *= inv; v.y *= inv; v.z *= inv; v.w *= inv;
            P4[c] = v;
        }
    }
}

// ---------------------------------------------------------------------------
// pv: O = P @ V, M=2048, N=512, K=(by+1)*128. grid (2,16,16).
// V[k][n] transposed into Bs during fill.
// ---------------------------------------------------------------------------
__global__ __launch_bounds__(256) void pv_kernel()
{
    const int z = blockIdx.z;
    const int m0 = blockIdx.y * 128, n0 = blockIdx.x * 256;
    const int ntiles = (blockIdx.y + 1) * 8;

    const float* P = g_p + (size_t)z * 4194304;
    const float* V = g_v + (size_t)z * 1048576;
    float* O = g_att + (size_t)z * 1048576;

    __shared__ __align__(16) unsigned As[128 * SSTR];
    __shared__ __align__(16) unsigned Bs[256 * SSTR];

    const int tid = threadIdx.x;
    const int w = tid >> 5, lane = tid & 31, g = lane >> 2, tg = lane & 3;
    const int wm = w >> 2, wn = w & 3;

    ACC_INIT

    const int arow = tid >> 2, ak4 = (tid & 3) * 4;
    const int bn4 = tid >> 4, bkr = tid & 15;   // bn4 0..15 (+16/it), bkr 0..15
    float4 pa[2], pb[4];
#pragma unroll
    for (int it = 0; it < 2; it++)
        pa[it] = *(const float4*)(P + (size_t)(m0 + arow + it * 64) * 2048 + ak4);
#pragma unroll
    for (int it = 0; it < 4; it++)
        pb[it] = *(const float4*)(V + (size_t)bkr * 512 + n0 + (bn4 + it * 16) * 4);

    for (int kt = 0; kt < ntiles; kt++) {
#pragma unroll
        for (int it = 0; it < 2; it++)
            *(uint4*)&As[(arow + it * 64) * SSTR + ak4] = f4tf(pa[it]);
#pragma unroll
        for (int it = 0; it < 4; it++) {
            int nb = (bn4 + it * 16) * 4;
            Bs[(nb + 0) * SSTR + bkr] = f2tf(pb[it].x);
            Bs[(nb + 1) * SSTR + bkr] = f2tf(pb[it].y);
            Bs[(nb + 2) * SSTR + bkr] = f2tf(pb[it].z);
            Bs[(nb + 3) * SSTR + bkr] = f2tf(pb[it].w);
        }
        __syncthreads();
        if (kt < ntiles - 1) {
            int k0 = (kt + 1) * 16;
#pragma unroll
            for (int it = 0; it < 2; it++)
                pa[it] = *(const float4*)(P + (size_t)(m0 + arow + it * 64) * 2048 + k0 + ak4);
#pragma unroll
            for (int it = 0; it < 4; it++)
                pb[it] = *(const float4*)(V + (size_t)(k0 + bkr) * 512 + n0 + (bn4 + it * 16) * 4);
        }
        compute_tile(As, Bs, acc, wm, wn, g, tg);
        __syncthreads();
    }

#pragma unroll
    for (int mi = 0; mi < 4; mi++)
#pragma unroll
        for (int ni = 0; ni < 8; ni++) {
            int col = n0 + wn * 64 + ni * 8 + 2 * tg;
#pragma unroll
            for (int rr = 0; rr < 2; rr++) {
                int row = m0 + wm * 64 + mi * 16 + g + rr * 8;
                float2 v = make_float2(acc[mi][ni][rr * 2], acc[mi][ni][rr * 2 + 1]);
                *(float2*)(O + (size_t)row * 512 + col) = v;
            }
        }
}

// ---------------------------------------------------------------------------
// final: out = concat(att) @ Wc^T + bc, M=4096, N=512, K=4096. grid (2,32)
// ---------------------------------------------------------------------------
__global__ __launch_bounds__(256) void final_kernel(const float* __restrict__ Wc,
                                                    const float* __restrict__ bc,
                                                    float* __restrict__ out)
{
    __shared__ __align__(16) unsigned As[128 * SSTR];
    __shared__ __align__(16) unsigned Bs[256 * SSTR];

    const int m0 = blockIdx.y * 128, n0 = blockIdx.x * 256;
    const int tid = threadIdx.x;
    const int w = tid >> 5, lane = tid & 31, g = lane >> 2, tg = lane & 3;
    const int wm = w >> 2, wn = w & 3;

    ACC_INIT

    const int arow = tid >> 2, ak4 = (tid & 3) * 4;
    float4 pa[2], pb[4];
#pragma unroll
    for (int it = 0; it < 2; it++) {
        int gi = m0 + arow + it * 64, bb = gi >> 11, t = gi & 2047;
        int h = ak4 >> 9, e = ak4 & 511;
        pa[it] = *(const float4*)(g_att + (((size_t)(bb * 8 + h) * 2048 + t) << 9) + e);
    }
#pragma unroll
    for (int it = 0; it < 4; it++)
        pb[it] = *(const float4*)(Wc + (size_t)(n0 + arow + it * 64) * 4096 + ak4);

    for (int kt = 0; kt < 256; kt++) {
#pragma unroll
        for (int it = 0; it < 2; it++)
            *(uint4*)&As[(arow + it * 64) * SSTR + ak4] = f4tf(pa[it]);
#pragma unroll
        for (int it = 0; it < 4; it++)
            *(uint4*)&Bs[(arow + it * 64) * SSTR + ak4] = f4tf(pb[it]);
        __syncthreads();
        if (kt < 255) {
            int k0 = (kt + 1) * 16;
#pragma unroll
            for (int it = 0; it < 2; it++) {
                int gi = m0 + arow + it * 64, bb = gi >> 11, t = gi & 2047;
                int k = k0 + ak4, h = k >> 9, e = k & 511;
                pa[it] = *(const float4*)(g_att + (((size_t)(bb * 8 + h) * 2048 + t) << 9) + e);
            }
#pragma unroll
            for (int it = 0; it < 4; it++)
                pb[it] = *(const float4*)(Wc + (size_t)(n0 + arow + it * 64) * 4096 + k0 + ak4);
        }
        compute_tile(As, Bs, acc, wm, wn, g, tg);
        __syncthreads();
    }

#pragma unroll
    for (int mi = 0; mi < 4; mi++)
#pragma unroll
        for (int ni = 0; ni < 8; ni++) {
            int col = n0 + wn * 64 + ni * 8 + 2 * tg;
            float2 bias = *(const float2*)(bc + col);
#pragma unroll
            for (int rr = 0; rr < 2; rr++) {
                int row = m0 + wm * 64 + mi * 16 + g + rr * 8;
                float2 v = make_float2(acc[mi][ni][rr * 2] + bias.x,
                                       acc[mi][ni][rr * 2 + 1] + bias.y);
                *(float2*)(out + (size_t)row * 512 + col) = v;
            }
        }
}

// ---------------------------------------------------------------------------
extern "C" void kernel_launch(void* const* d_in, const int* in_sizes, int n_in,
                              void* d_out, int out_size)
{
    (void)in_sizes; (void)n_in; (void)out_size;
    const float* x  = (const float*)d_in[0];
    const float* Wk = (const float*)d_in[1];
    const float* Wq = (const float*)d_in[2];
    const float* Wv = (const float*)d_in[3];
    const float* Wc = (const float*)d_in[4];
    const float* bc = (const float*)d_in[5];
    float* out = (float*)d_out;

    dim3 blk(256);

    proj_kernel<<<dim3(16, 32), blk>>>(x, Wq, 0);
    proj_kernel<<<dim3(16, 32), blk>>>(x, Wk, 1);
    proj_kernel<<<dim3(16, 32), blk>>>(x, Wv, 2);

    scores_kernel<<<dim3(8, 16, 16), blk>>>();
    softmax_kernel<<<dim3(32768), blk>>>();
    pv_kernel<<<dim3(2, 16, 16), blk>>>();

    final_kernel<<<dim3(2, 32), blk>>>(Wc, bc, out);
}

// round 5
// speedup vs baseline: 1.0245x; 1.0245x over previous
#include <cuda_runtime.h>

// ---------------------------------------------------------------------------
// MultiHeadAttention b=2,t=2048,e=512,h=8
// Round 4: TF32 mma.sync, block 128x256, warp 64x64, DOUBLE-BUFFERED smem
// (one __syncthreads per k-tile), fused QKV projection, longest-first blocks.
// ---------------------------------------------------------------------------

#define NEG_INF (-1e30f)
#define SCALE 0.044194173824159216f   // 1/sqrt(512)
#define SSTR 20                       // smem row stride (words), conflict-free

#define A_WORDS (128 * SSTR)
#define B_WORDS (256 * SSTR)
#define SMEM_BYTES ((2 * A_WORDS + 2 * B_WORDS) * 4)   // 61440

static __device__ float g_q[16 * 2048 * 512];
static __device__ float g_k[16 * 2048 * 512];
static __device__ float g_v[16 * 2048 * 512];
static __device__ float g_p[16u * 2048 * 2048];
static __device__ float g_att[16 * 2048 * 512];

__device__ __forceinline__ unsigned f2tf(float x) {
    unsigned r; asm("cvt.rna.tf32.f32 %0, %1;" : "=r"(r) : "f"(x)); return r;
}
__device__ __forceinline__ uint4 f4tf(float4 v) {
    return make_uint4(f2tf(v.x), f2tf(v.y), f2tf(v.z), f2tf(v.w));
}
__device__ __forceinline__ void mma8(float* d, const unsigned* a, const unsigned* b) {
    asm volatile("mma.sync.aligned.m16n8k8.row.col.f32.tf32.tf32.f32 "
                 "{%0,%1,%2,%3}, {%4,%5,%6,%7}, {%8,%9}, {%0,%1,%2,%3};"
                 : "+f"(d[0]), "+f"(d[1]), "+f"(d[2]), "+f"(d[3])
                 : "r"(a[0]), "r"(a[1]), "r"(a[2]), "r"(a[3]),
                   "r"(b[0]), "r"(b[1]));
}

// One 128x256x16 tile: As 128 rows (M), Bs 256 rows (N), [row][k] stride SSTR.
__device__ __forceinline__ void compute_tile(const unsigned* __restrict__ As,
                                             const unsigned* __restrict__ Bs,
                                             float acc[4][8][4],
                                             int wm, int wn, int g, int tg)
{
#pragma unroll
    for (int kk = 0; kk < 16; kk += 8) {
        unsigned af[4][4];
#pragma unroll
        for (int mi = 0; mi < 4; mi++) {
            const unsigned* p = As + (wm * 64 + mi * 16 + g) * SSTR + kk + tg;
            af[mi][0] = p[0];
            af[mi][1] = p[8 * SSTR];
            af[mi][2] = p[4];
            af[mi][3] = p[8 * SSTR + 4];
        }
        unsigned bf[8][2];
#pragma unroll
        for (int ni = 0; ni < 8; ni++) {
            const unsigned* p = Bs + (wn * 64 + ni * 8 + g) * SSTR + kk + tg;
            bf[ni][0] = p[0];
            bf[ni][1] = p[4];
        }
#pragma unroll
        for (int mi = 0; mi < 4; mi++)
#pragma unroll
            for (int ni = 0; ni < 8; ni++)
                mma8(acc[mi][ni], af[mi], bf[ni]);
    }
}

#define ACC_INIT float acc[4][8][4]; \
    _Pragma("unroll") for (int i = 0; i < 4; i++) \
    _Pragma("unroll") for (int j = 0; j < 8; j++) \
    _Pragma("unroll") for (int k = 0; k < 4; k++) acc[i][j][k] = 0.f;

#define SMEM_DECL \
    extern __shared__ unsigned smemraw[]; \
    unsigned* AsB = smemraw; \
    unsigned* BsB = smemraw + 2 * A_WORDS;

#define STS_TILE(stage) do { \
    unsigned* As_ = AsB + (stage) * A_WORDS; \
    unsigned* Bs_ = BsB + (stage) * B_WORDS; \
    _Pragma("unroll") for (int it = 0; it < 2; it++) \
        *(uint4*)&As_[(arow + it * 64) * SSTR + ak4] = f4tf(pa[it]); \
    _Pragma("unroll") for (int it = 0; it < 4; it++) \
        *(uint4*)&Bs_[(arow + it * 64) * SSTR + ak4] = f4tf(pb[it]); \
} while (0)

// ---------------------------------------------------------------------------
// fused QKV proj: C = X * W^T, M=4096, N=4096, K=512. grid (16,32,3)
// ---------------------------------------------------------------------------
__global__ __launch_bounds__(256) void proj_kernel(const float* __restrict__ X,
                                                   const float* __restrict__ Wq,
                                                   const float* __restrict__ Wk,
                                                   const float* __restrict__ Wv)
{
    SMEM_DECL
    const int z = blockIdx.z;
    const float* W = (z == 0) ? Wq : (z == 1) ? Wk : Wv;
    float* out = (z == 0) ? g_q : (z == 1) ? g_k : g_v;

    const int m0 = blockIdx.y * 128, n0 = blockIdx.x * 256;
    const int tid = threadIdx.x;
    const int w = tid >> 5, lane = tid & 31, g = lane >> 2, tg = lane & 3;
    const int wm = w >> 2, wn = w & 3;
    const int arow = tid >> 2, ak4 = (tid & 3) * 4;

    ACC_INIT
    float4 pa[2], pb[4];

#define LDG_PROJ(k0) do { \
    _Pragma("unroll") for (int it = 0; it < 2; it++) \
        pa[it] = *(const float4*)(X + (size_t)(m0 + arow + it * 64) * 512 + (k0) + ak4); \
    _Pragma("unroll") for (int it = 0; it < 4; it++) \
        pb[it] = *(const float4*)(W + (size_t)(n0 + arow + it * 64) * 512 + (k0) + ak4); \
} while (0)

    LDG_PROJ(0);
    STS_TILE(0);
    LDG_PROJ(16);
    __syncthreads();

    const int nt = 32;
    for (int kt = 0; kt < nt; kt++) {
        if (kt + 1 < nt) STS_TILE((kt + 1) & 1);
        if (kt + 2 < nt) LDG_PROJ((kt + 2) * 16);
        compute_tile(AsB + (kt & 1) * A_WORDS, BsB + (kt & 1) * B_WORDS,
                     acc, wm, wn, g, tg);
        __syncthreads();
    }

#pragma unroll
    for (int mi = 0; mi < 4; mi++)
#pragma unroll
        for (int ni = 0; ni < 8; ni++) {
            int cbase = n0 + wn * 64 + ni * 8 + 2 * tg;
            int h = cbase >> 9, e = cbase & 511;
#pragma unroll
            for (int rr = 0; rr < 2; rr++) {
                int row = m0 + wm * 64 + mi * 16 + g + rr * 8;
                int bb = row >> 11, t = row & 2047;
                float2 v = make_float2(acc[mi][ni][rr * 2], acc[mi][ni][rr * 2 + 1]);
                *(float2*)(out + (((size_t)(bb * 8 + h) * 2048 + t) << 9) + e) = v;
            }
        }
}

// ---------------------------------------------------------------------------
// scores: S = Q K^T * scale + causal. grid (8,16,16); y reversed.
// ---------------------------------------------------------------------------
__global__ __launch_bounds__(256) void scores_kernel()
{
    SMEM_DECL
    const int z = blockIdx.z;
    const int m0 = (15 - blockIdx.y) * 128, n0 = blockIdx.x * 256;
    if (n0 > m0 + 127) return;

    const float* Q = g_q + (size_t)z * 1048576;
    const float* K = g_k + (size_t)z * 1048576;
    float* P = g_p + (size_t)z * 4194304;

    const int tid = threadIdx.x;
    const int w = tid >> 5, lane = tid & 31, g = lane >> 2, tg = lane & 3;
    const int wm = w >> 2, wn = w & 3;
    const int arow = tid >> 2, ak4 = (tid & 3) * 4;

    ACC_INIT
    float4 pa[2], pb[4];

#define LDG_SC(k0) do { \
    _Pragma("unroll") for (int it = 0; it < 2; it++) \
        pa[it] = *(const float4*)(Q + (size_t)(m0 + arow + it * 64) * 512 + (k0) + ak4); \
    _Pragma("unroll") for (int it = 0; it < 4; it++) \
        pb[it] = *(const float4*)(K + (size_t)(n0 + arow + it * 64) * 512 + (k0) + ak4); \
} while (0)

    LDG_SC(0);
    STS_TILE(0);
    LDG_SC(16);
    __syncthreads();

    const int nt = 32;
    for (int kt = 0; kt < nt; kt++) {
        if (kt + 1 < nt) STS_TILE((kt + 1) & 1);
        if (kt + 2 < nt) LDG_SC((kt + 2) * 16);
        compute_tile(AsB + (kt & 1) * A_WORDS, BsB + (kt & 1) * B_WORDS,
                     acc, wm, wn, g, tg);
        __syncthreads();
    }

#pragma unroll
    for (int mi = 0; mi < 4; mi++)
#pragma unroll
        for (int ni = 0; ni < 8; ni++) {
            int col = n0 + wn * 64 + ni * 8 + 2 * tg;
#pragma unroll
            for (int rr = 0; rr < 2; rr++) {
                int row = m0 + wm * 64 + mi * 16 + g + rr * 8;
                float2 v;
                v.x = (col <= row) ? acc[mi][ni][rr * 2] * SCALE : NEG_INF;
                v.y = (col + 1 <= row) ? acc[mi][ni][rr * 2 + 1] * SCALE : NEG_INF;
                *(float2*)(P + (size_t)row * 2048 + col) = v;
            }
        }
}

// ---------------------------------------------------------------------------
// softmax: one block/row, float4, single read+write.
// ---------------------------------------------------------------------------
__global__ __launch_bounds__(256) void softmax_kernel()
{
    const int row = blockIdx.x;
    const int z = row >> 11;
    const int q = row & 2047;
    float4* P4 = (float4*)(g_p + (size_t)z * 4194304 + (size_t)q * 2048);
    const int end4 = (((q >> 7) + 1) << 7) >> 2;

    const int tid = threadIdx.x;
    const int lane = tid & 31, wid = tid >> 5;
    __shared__ float red[8];

    float4 vals[2];
    float m = -3.4e38f;
#pragma unroll
    for (int it = 0; it < 2; it++) {
        int c = tid + it * 256;
        if (c < end4) {
            float4 v = P4[c];
            vals[it] = v;
            m = fmaxf(m, fmaxf(fmaxf(v.x, v.y), fmaxf(v.z, v.w)));
        }
    }
#pragma unroll
    for (int s = 16; s > 0; s >>= 1) m = fmaxf(m, __shfl_xor_sync(~0u, m, s));
    if (lane == 0) red[wid] = m;
    __syncthreads();
    m = red[0];
#pragma unroll
    for (int i = 1; i < 8; i++) m = fmaxf(m, red[i]);

    float sum = 0.f;
#pragma unroll
    for (int it = 0; it < 2; it++) {
        int c = tid + it * 256;
        if (c < end4) {
            float4 v = vals[it];
            v.x = expf(v.x - m); v.y = expf(v.y - m);
            v.z = expf(v.z - m); v.w = expf(v.w - m);
            vals[it] = v;
            sum += v.x + v.y + v.z + v.w;
        }
    }
#pragma unroll
    for (int s = 16; s > 0; s >>= 1) sum += __shfl_xor_sync(~0u, sum, s);
    __syncthreads();
    if (lane == 0) red[wid] = sum;
    __syncthreads();
    sum = 0.f;
#pragma unroll
    for (int i = 0; i < 8; i++) sum += red[i];
    const float inv = 1.f / sum;

#pragma unroll
    for (int it = 0; it < 2; it++) {
        int c = tid + it * 256;
        if (c < end4) {
            float4 v = vals[it];
            v.x *= inv; v.y *= inv; v.z *= inv; v.w *= inv;
            P4[c] = v;
        }
    }
}

// ---------------------------------------------------------------------------
// pv: O = P @ V. grid (2,16,16); y reversed (longest-first).
// ---------------------------------------------------------------------------
__global__ __launch_bounds__(256) void pv_kernel()
{
    SMEM_DECL
    const int z = blockIdx.z;
    const int by = 15 - blockIdx.y;
    const int m0 = by * 128, n0 = blockIdx.x * 256;
    const int nt = (by + 1) * 8;

    const float* P = g_p + (size_t)z * 4194304;
    const float* V = g_v + (size_t)z * 1048576;
    float* O = g_att + (size_t)z * 1048576;

    const int tid = threadIdx.x;
    const int w = tid >> 5, lane = tid & 31, g = lane >> 2, tg = lane & 3;
    const int wm = w >> 2, wn = w & 3;
    const int arow = tid >> 2, ak4 = (tid & 3) * 4;
    const int bn4 = tid >> 4, bkr = tid & 15;

    ACC_INIT
    float4 pa[2], pb[4];

#define LDG_PV(k0) do { \
    _Pragma("unroll") for (int it = 0; it < 2; it++) \
        pa[it] = *(const float4*)(P + (size_t)(m0 + arow + it * 64) * 2048 + (k0) + ak4); \
    _Pragma("unroll") for (int it = 0; it < 4; it++) \
        pb[it] = *(const float4*)(V + (size_t)((k0) + bkr) * 512 + n0 + (bn4 + it * 16) * 4); \
} while (0)

#define STS_PV(stage) do { \
    unsigned* As_ = AsB + (stage) * A_WORDS; \
    unsigned* Bs_ = BsB + (stage) * B_WORDS; \
    _Pragma("unroll") for (int it = 0; it < 2; it++) \
        *(uint4*)&As_[(arow + it * 64) * SSTR + ak4] = f4tf(pa[it]); \
    _Pragma("unroll") for (int it = 0; it < 4; it++) { \
        int nb = (bn4 + it * 16) * 4; \
        Bs_[(nb + 0) * SSTR + bkr] = f2tf(pb[it].x); \
        Bs_[(nb + 1) * SSTR + bkr] = f2tf(pb[it].y); \
        Bs_[(nb + 2) * SSTR + bkr] = f2tf(pb[it].z); \
        Bs_[(nb + 3) * SSTR + bkr] = f2tf(pb[it].w); \
    } \
} while (0)

    LDG_PV(0);
    STS_PV(0);
    if (nt > 1) LDG_PV(16);
    __syncthreads();

    for (int kt = 0; kt < nt; kt++) {
        if (kt + 1 < nt) STS_PV((kt + 1) & 1);
        if (kt + 2 < nt) LDG_PV((kt + 2) * 16);
        compute_tile(AsB + (kt & 1) * A_WORDS, BsB + (kt & 1) * B_WORDS,
                     acc, wm, wn, g, tg);
        __syncthreads();
    }

#pragma unroll
    for (int mi = 0; mi < 4; mi++)
#pragma unroll
        for (int ni = 0; ni < 8; ni++) {
            int col = n0 + wn * 64 + ni * 8 + 2 * tg;
#pragma unroll
            for (int rr = 0; rr < 2; rr++) {
                int row = m0 + wm * 64 + mi * 16 + g + rr * 8;
                float2 v = make_float2(acc[mi][ni][rr * 2], acc[mi][ni][rr * 2 + 1]);
                *(float2*)(O + (size_t)row * 512 + col) = v;
            }
        }
}

// ---------------------------------------------------------------------------
// final: out = concat(att) @ Wc^T + bc. grid (2,32).
// ---------------------------------------------------------------------------
__global__ __launch_bounds__(256) void final_kernel(const float* __restrict__ Wc,
                                                    const float* __restrict__ bc,
                                                    float* __restrict__ out)
{
    SMEM_DECL
    const int m0 = blockIdx.y * 128, n0 = blockIdx.x * 256;
    const int tid = threadIdx.x;
    const int w = tid >> 5, lane = tid & 31, g = lane >> 2, tg = lane & 3;
    const int wm = w >> 2, wn = w & 3;
    const int arow = tid >> 2, ak4 = (tid & 3) * 4;

    ACC_INIT
    float4 pa[2], pb[4];

    const int gi0 = m0 + arow, bb0 = gi0 >> 11, t0 = gi0 & 2047;
    const int gi1 = gi0 + 64, bb1 = gi1 >> 11, t1 = gi1 & 2047;

#define LDG_FIN(k0) do { \
    { int k = (k0) + ak4, h = k >> 9, e = k & 511; \
      pa[0] = *(const float4*)(g_att + (((size_t)(bb0 * 8 + h) * 2048 + t0) << 9) + e); \
      pa[1] = *(const float4*)(g_att + (((size_t)(bb1 * 8 + h) * 2048 + t1) << 9) + e); } \
    _Pragma("unroll") for (int it = 0; it < 4; it++) \
        pb[it] = *(const float4*)(Wc + (size_t)(n0 + arow + it * 64) * 4096 + (k0) + ak4); \
} while (0)

    LDG_FIN(0);
    STS_TILE(0);
    LDG_FIN(16);
    __syncthreads();

    const int nt = 256;
    for (int kt = 0; kt < nt; kt++) {
        if (kt + 1 < nt) STS_TILE((kt + 1) & 1);
        if (kt + 2 < nt) LDG_FIN((kt + 2) * 16);
        compute_tile(AsB + (kt & 1) * A_WORDS, BsB + (kt & 1) * B_WORDS,
                     acc, wm, wn, g, tg);
        __syncthreads();
    }

#pragma unroll
    for (int mi = 0; mi < 4; mi++)
#pragma unroll
        for (int ni = 0; ni < 8; ni++) {
            int col = n0 + wn * 64 + ni * 8 + 2 * tg;
            float2 bias = *(const float2*)(bc + col);
#pragma unroll
            for (int rr = 0; rr < 2; rr++) {
                int row = m0 + wm * 64 + mi * 16 + g + rr * 8;
                float2 v = make_float2(acc[mi][ni][rr * 2] + bias.x,
                                       acc[mi][ni][rr * 2 + 1] + bias.y);
                *(float2*)(out + (size_t)row * 512 + col) = v;
            }
        }
}

// ---------------------------------------------------------------------------
extern "C" void kernel_launch(void* const* d_in, const int* in_sizes, int n_in,
                              void* d_out, int out_size)
{
    (void)in_sizes; (void)n_in; (void)out_size;
    const float* x  = (const float*)d_in[0];
    const float* Wk = (const float*)d_in[1];
    const float* Wq = (const float*)d_in[2];
    const float* Wv = (const float*)d_in[3];
    const float* Wc = (const float*)d_in[4];
    const float* bc = (const float*)d_in[5];
    float* out = (float*)d_out;

    cudaFuncSetAttribute(proj_kernel,   cudaFuncAttributeMaxDynamicSharedMemorySize, SMEM_BYTES);
    cudaFuncSetAttribute(scores_kernel, cudaFuncAttributeMaxDynamicSharedMemorySize, SMEM_BYTES);
    cudaFuncSetAttribute(pv_kernel,     cudaFuncAttributeMaxDynamicSharedMemorySize, SMEM_BYTES);
    cudaFuncSetAttribute(final_kernel,  cudaFuncAttributeMaxDynamicSharedMemorySize, SMEM_BYTES);

    dim3 blk(256);

    proj_kernel<<<dim3(16, 32, 3), blk, SMEM_BYTES>>>(x, Wq, Wk, Wv);
    scores_kernel<<<dim3(8, 16, 16), blk, SMEM_BYTES>>>();
    softmax_kernel<<<dim3(32768), blk>>>();
    pv_kernel<<<dim3(2, 16, 16), blk, SMEM_BYTES>>>();
    final_kernel<<<dim3(2, 32), blk, SMEM_BYTES>>>(Wc, bc, out);
}

// round 6
// speedup vs baseline: 1.1737x; 1.1456x over previous
#include <cuda_runtime.h>

// ---------------------------------------------------------------------------
// MultiHeadAttention b=2,t=2048,e=512,h=8
// Round 5: TF32 mma.sync, block 128x128 / warp 64x32 (2 CTA/SM), smem
// double-buffered with ONE __syncthreads per k-tile, fused QKV projection.
// ---------------------------------------------------------------------------

#define NEG_INF (-1e30f)
#define SCALE 0.044194173824159216f   // 1/sqrt(512)
#define SSTR 20                       // smem row stride (words), conflict-free

#define T_WORDS (128 * SSTR)          // one A or B stage

static __device__ float g_q[16 * 2048 * 512];
static __device__ float g_k[16 * 2048 * 512];
static __device__ float g_v[16 * 2048 * 512];
static __device__ float g_p[16u * 2048 * 2048];
static __device__ float g_att[16 * 2048 * 512];

__device__ __forceinline__ unsigned f2tf(float x) {
    unsigned r; asm("cvt.rna.tf32.f32 %0, %1;" : "=r"(r) : "f"(x)); return r;
}
__device__ __forceinline__ uint4 f4tf(float4 v) {
    return make_uint4(f2tf(v.x), f2tf(v.y), f2tf(v.z), f2tf(v.w));
}
__device__ __forceinline__ void mma8(float* d, const unsigned* a, const unsigned* b) {
    asm volatile("mma.sync.aligned.m16n8k8.row.col.f32.tf32.tf32.f32 "
                 "{%0,%1,%2,%3}, {%4,%5,%6,%7}, {%8,%9}, {%0,%1,%2,%3};"
                 : "+f"(d[0]), "+f"(d[1]), "+f"(d[2]), "+f"(d[3])
                 : "r"(a[0]), "r"(a[1]), "r"(a[2]), "r"(a[3]),
                   "r"(b[0]), "r"(b[1]));
}

// One 128x128x16 tile: As/Bs 128 rows [row][k], stride SSTR. Warp (wm,wn) does 64x32.
__device__ __forceinline__ void compute_tile(const unsigned* __restrict__ As,
                                             const unsigned* __restrict__ Bs,
                                             float acc[4][4][4],
                                             int wm, int wn, int g, int tg)
{
#pragma unroll
    for (int kk = 0; kk < 16; kk += 8) {
        unsigned af[4][4];
#pragma unroll
        for (int mi = 0; mi < 4; mi++) {
            const unsigned* p = As + (wm * 64 + mi * 16 + g) * SSTR + kk + tg;
            af[mi][0] = p[0];
            af[mi][1] = p[8 * SSTR];
            af[mi][2] = p[4];
            af[mi][3] = p[8 * SSTR + 4];
        }
        unsigned bf[4][2];
#pragma unroll
        for (int ni = 0; ni < 4; ni++) {
            const unsigned* p = Bs + (wn * 32 + ni * 8 + g) * SSTR + kk + tg;
            bf[ni][0] = p[0];
            bf[ni][1] = p[4];
        }
#pragma unroll
        for (int mi = 0; mi < 4; mi++)
#pragma unroll
            for (int ni = 0; ni < 4; ni++)
                mma8(acc[mi][ni], af[mi], bf[ni]);
    }
}

#define ACC_INIT float acc[4][4][4]; \
    _Pragma("unroll") for (int i = 0; i < 4; i++) \
    _Pragma("unroll") for (int j = 0; j < 4; j++) \
    _Pragma("unroll") for (int k = 0; k < 4; k++) acc[i][j][k] = 0.f;

#define SMEM_DECL \
    __shared__ __align__(16) unsigned AsB[2 * T_WORDS]; \
    __shared__ __align__(16) unsigned BsB[2 * T_WORDS];

// Standard fill: both A and B are [row][k] with row = tid>>1-style mapping.
// row covers 0..127 via l = tid + it*256 -> row = l>>2 (0..127), k4 = (l&3)*4.
#define STS_STD(stage) do { \
    unsigned* As_ = AsB + (stage) * T_WORDS; \
    unsigned* Bs_ = BsB + (stage) * T_WORDS; \
    _Pragma("unroll") for (int it = 0; it < 2; it++) { \
        int row = (tid + it * 256) >> 2; \
        *(uint4*)&As_[row * SSTR + ak4] = f4tf(pa[it]); \
        *(uint4*)&Bs_[row * SSTR + ak4] = f4tf(pb[it]); \
    } \
} while (0)

// ---------------------------------------------------------------------------
// fused QKV proj: C = X * W^T, M=N=4096, K=512. grid (32,32,3)
// ---------------------------------------------------------------------------
__global__ __launch_bounds__(256) void proj_kernel(const float* __restrict__ X,
                                                   const float* __restrict__ Wq,
                                                   const float* __restrict__ Wk,
                                                   const float* __restrict__ Wv)
{
    SMEM_DECL
    const int z = blockIdx.z;
    const float* W = (z == 0) ? Wq : (z == 1) ? Wk : Wv;
    float* out = (z == 0) ? g_q : (z == 1) ? g_k : g_v;

    const int m0 = blockIdx.y * 128, n0 = blockIdx.x * 128;
    const int tid = threadIdx.x;
    const int w = tid >> 5, lane = tid & 31, g = lane >> 2, tg = lane & 3;
    const int wm = w >> 2, wn = w & 3;
    const int ak4 = (tid & 3) * 4;

    ACC_INIT
    float4 pa[2], pb[2];

#define LDG_PROJ(k0) do { \
    _Pragma("unroll") for (int it = 0; it < 2; it++) { \
        int row = (tid + it * 256) >> 2; \
        pa[it] = *(const float4*)(X + (size_t)(m0 + row) * 512 + (k0) + ak4); \
        pb[it] = *(const float4*)(W + (size_t)(n0 + row) * 512 + (k0) + ak4); \
    } \
} while (0)

    LDG_PROJ(0);
    STS_STD(0);
    LDG_PROJ(16);
    __syncthreads();

    const int nt = 32;
    for (int kt = 0; kt < nt; kt++) {
        if (kt + 1 < nt) STS_STD((kt + 1) & 1);
        if (kt + 2 < nt) LDG_PROJ((kt + 2) * 16);
        compute_tile(AsB + (kt & 1) * T_WORDS, BsB + (kt & 1) * T_WORDS,
                     acc, wm, wn, g, tg);
        __syncthreads();
    }

#pragma unroll
    for (int mi = 0; mi < 4; mi++)
#pragma unroll
        for (int ni = 0; ni < 4; ni++) {
            int cbase = n0 + wn * 32 + ni * 8 + 2 * tg;
            int h = cbase >> 9, e = cbase & 511;
#pragma unroll
            for (int rr = 0; rr < 2; rr++) {
                int row = m0 + wm * 64 + mi * 16 + g + rr * 8;
                int bb = row >> 11, t = row & 2047;
                float2 v = make_float2(acc[mi][ni][rr * 2], acc[mi][ni][rr * 2 + 1]);
                *(float2*)(out + (((size_t)(bb * 8 + h) * 2048 + t) << 9) + e) = v;
            }
        }
}

// ---------------------------------------------------------------------------
// scores: S = Q K^T * scale + causal. grid (16,16,16), y reversed.
// ---------------------------------------------------------------------------
__global__ __launch_bounds__(256) void scores_kernel()
{
    SMEM_DECL
    const int z = blockIdx.z;
    const int m0 = (15 - blockIdx.y) * 128, n0 = blockIdx.x * 128;
    if (n0 > m0 + 127) return;

    const float* Q = g_q + (size_t)z * 1048576;
    const float* K = g_k + (size_t)z * 1048576;
    float* P = g_p + (size_t)z * 4194304;

    const int tid = threadIdx.x;
    const int w = tid >> 5, lane = tid & 31, g = lane >> 2, tg = lane & 3;
    const int wm = w >> 2, wn = w & 3;
    const int ak4 = (tid & 3) * 4;

    ACC_INIT
    float4 pa[2], pb[2];

#define LDG_SC(k0) do { \
    _Pragma("unroll") for (int it = 0; it < 2; it++) { \
        int row = (tid + it * 256) >> 2; \
        pa[it] = *(const float4*)(Q + (size_t)(m0 + row) * 512 + (k0) + ak4); \
        pb[it] = *(const float4*)(K + (size_t)(n0 + row) * 512 + (k0) + ak4); \
    } \
} while (0)

    LDG_SC(0);
    STS_STD(0);
    LDG_SC(16);
    __syncthreads();

    const int nt = 32;
    for (int kt = 0; kt < nt; kt++) {
        if (kt + 1 < nt) STS_STD((kt + 1) & 1);
        if (kt + 2 < nt) LDG_SC((kt + 2) * 16);
        compute_tile(AsB + (kt & 1) * T_WORDS, BsB + (kt & 1) * T_WORDS,
                     acc, wm, wn, g, tg);
        __syncthreads();
    }

#pragma unroll
    for (int mi = 0; mi < 4; mi++)
#pragma unroll
        for (int ni = 0; ni < 4; ni++) {
            int col = n0 + wn * 32 + ni * 8 + 2 * tg;
#pragma unroll
            for (int rr = 0; rr < 2; rr++) {
                int row = m0 + wm * 64 + mi * 16 + g + rr * 8;
                float2 v;
                v.x = (col <= row) ? acc[mi][ni][rr * 2] * SCALE : NEG_INF;
                v.y = (col + 1 <= row) ? acc[mi][ni][rr * 2 + 1] * SCALE : NEG_INF;
                *(float2*)(P + (size_t)row * 2048 + col) = v;
            }
        }
}

// ---------------------------------------------------------------------------
// softmax: one block/row, float4, single read+write.
// ---------------------------------------------------------------------------
__global__ __launch_bounds__(256) void softmax_kernel()
{
    const int row = blockIdx.x;
    const int z = row >> 11;
    const int q = row & 2047;
    float4* P4 = (float4*)(g_p + (size_t)z * 4194304 + (size_t)q * 2048);
    const int end4 = (((q >> 7) + 1) << 7) >> 2;

    const int tid = threadIdx.x;
    const int lane = tid & 31, wid = tid >> 5;
    __shared__ float red[8];

    float4 vals[2];
    float m = -3.4e38f;
#pragma unroll
    for (int it = 0; it < 2; it++) {
        int c = tid + it * 256;
        if (c < end4) {
            float4 v = P4[c];
            vals[it] = v;
            m = fmaxf(m, fmaxf(fmaxf(v.x, v.y), fmaxf(v.z, v.w)));
        }
    }
#pragma unroll
    for (int s = 16; s > 0; s >>= 1) m = fmaxf(m, __shfl_xor_sync(~0u, m, s));
    if (lane == 0) red[wid] = m;
    __syncthreads();
    m = red[0];
#pragma unroll
    for (int i = 1; i < 8; i++) m = fmaxf(m, red[i]);

    float sum = 0.f;
#pragma unroll
    for (int it = 0; it < 2; it++) {
        int c = tid + it * 256;
        if (c < end4) {
            float4 v = vals[it];
            v.x = expf(v.x - m); v.y = expf(v.y - m);
            v.z = expf(v.z - m); v.w = expf(v.w - m);
            vals[it] = v;
            sum += v.x + v.y + v.z + v.w;
        }
    }
#pragma unroll
    for (int s = 16; s > 0; s >>= 1) sum += __shfl_xor_sync(~0u, sum, s);
    __syncthreads();
    if (lane == 0) red[wid] = sum;
    __syncthreads();
    sum = 0.f;
#pragma unroll
    for (int i = 0; i < 8; i++) sum += red[i];
    const float inv = 1.f / sum;

#pragma unroll
    for (int it = 0; it < 2; it++) {
        int c = tid + it * 256;
        if (c < end4) {
            float4 v = vals[it];
            v.x *= inv; v.y *= inv; v.z *= inv; v.w *= inv;
            P4[c] = v;
        }
    }
}

// ---------------------------------------------------------------------------
// pv: O = P @ V, M=2048, N=512, K=(by+1)*128. grid (4,16,16), y reversed.
// V[k][n] transposed into Bs.
// ---------------------------------------------------------------------------
__global__ __launch_bounds__(256) void pv_kernel()
{
    SMEM_DECL
    const int z = blockIdx.z;
    const int by = 15 - blockIdx.y;
    const int m0 = by * 128, n0 = blockIdx.x * 128;
    const int nt = (by + 1) * 8;

    const float* P = g_p + (size_t)z * 4194304;
    const float* V = g_v + (size_t)z * 1048576;
    float* O = g_att + (size_t)z * 1048576;

    const int tid = threadIdx.x;
    const int w = tid >> 5, lane = tid & 31, g = lane >> 2, tg = lane & 3;
    const int wm = w >> 2, wn = w & 3;
    const int ak4 = (tid & 3) * 4;
    const int bkr = tid & 15;

    ACC_INIT
    float4 pa[2], pb[2];

#define LDG_PV(k0) do { \
    _Pragma("unroll") for (int it = 0; it < 2; it++) { \
        int l = tid + it * 256; \
        int arow = l >> 2; \
        pa[it] = *(const float4*)(P + (size_t)(m0 + arow) * 2048 + (k0) + ak4); \
        int n4 = l >> 4; \
        pb[it] = *(const float4*)(V + (size_t)((k0) + bkr) * 512 + n0 + n4 * 4); \
    } \
} while (0)

#define STS_PV(stage) do { \
    unsigned* As_ = AsB + (stage) * T_WORDS; \
    unsigned* Bs_ = BsB + (stage) * T_WORDS; \
    _Pragma("unroll") for (int it = 0; it < 2; it++) { \
        int l = tid + it * 256; \
        int arow = l >> 2; \
        *(uint4*)&As_[arow * SSTR + ak4] = f4tf(pa[it]); \
        int nb = (l >> 4) * 4; \
        Bs_[(nb + 0) * SSTR + bkr] = f2tf(pb[it].x); \
        Bs_[(nb + 1) * SSTR + bkr] = f2tf(pb[it].y); \
        Bs_[(nb + 2) * SSTR + bkr] = f2tf(pb[it].z); \
        Bs_[(nb + 3) * SSTR + bkr] = f2tf(pb[it].w); \
    } \
} while (0)

    LDG_PV(0);
    STS_PV(0);
    if (nt > 1) LDG_PV(16);
    __syncthreads();

    for (int kt = 0; kt < nt; kt++) {
        if (kt + 1 < nt) STS_PV((kt + 1) & 1);
        if (kt + 2 < nt) LDG_PV((kt + 2) * 16);
        compute_tile(AsB + (kt & 1) * T_WORDS, BsB + (kt & 1) * T_WORDS,
                     acc, wm, wn, g, tg);
        __syncthreads();
    }

#pragma unroll
    for (int mi = 0; mi < 4; mi++)
#pragma unroll
        for (int ni = 0; ni < 4; ni++) {
            int col = n0 + wn * 32 + ni * 8 + 2 * tg;
#pragma unroll
            for (int rr = 0; rr < 2; rr++) {
                int row = m0 + wm * 64 + mi * 16 + g + rr * 8;
                float2 v = make_float2(acc[mi][ni][rr * 2], acc[mi][ni][rr * 2 + 1]);
                *(float2*)(O + (size_t)row * 512 + col) = v;
            }
        }
}

// ---------------------------------------------------------------------------
// final: out = concat(att) @ Wc^T + bc, M=4096, N=512, K=4096. grid (4,32)
// ---------------------------------------------------------------------------
__global__ __launch_bounds__(256) void final_kernel(const float* __restrict__ Wc,
                                                    const float* __restrict__ bc,
                                                    float* __restrict__ out)
{
    SMEM_DECL
    const int m0 = blockIdx.y * 128, n0 = blockIdx.x * 128;
    const int tid = threadIdx.x;
    const int w = tid >> 5, lane = tid & 31, g = lane >> 2, tg = lane & 3;
    const int wm = w >> 2, wn = w & 3;
    const int ak4 = (tid & 3) * 4;

    ACC_INIT
    float4 pa[2], pb[2];

#define LDG_FIN(k0) do { \
    _Pragma("unroll") for (int it = 0; it < 2; it++) { \
        int row = (tid + it * 256) >> 2; \
        int gi = m0 + row, bb = gi >> 11, t = gi & 2047; \
        int k = (k0) + ak4, h = k >> 9, e = k & 511; \
        pa[it] = *(const float4*)(g_att + (((size_t)(bb * 8 + h) * 2048 + t) << 9) + e); \
        pb[it] = *(const float4*)(Wc + (size_t)(n0 + row) * 4096 + k); \
    } \
} while (0)

    LDG_FIN(0);
    STS_STD(0);
    LDG_FIN(16);
    __syncthreads();

    const int nt = 256;
    for (int kt = 0; kt < nt; kt++) {
        if (kt + 1 < nt) STS_STD((kt + 1) & 1);
        if (kt + 2 < nt) LDG_FIN((kt + 2) * 16);
        compute_tile(AsB + (kt & 1) * T_WORDS, BsB + (kt & 1) * T_WORDS,
                     acc, wm, wn, g, tg);
        __syncthreads();
    }

#pragma unroll
    for (int mi = 0; mi < 4; mi++)
#pragma unroll
        for (int ni = 0; ni < 4; ni++) {
            int col = n0 + wn * 32 + ni * 8 + 2 * tg;
            float2 bias = *(const float2*)(bc + col);
#pragma unroll
            for (int rr = 0; rr < 2; rr++) {
                int row = m0 + wm * 64 + mi * 16 + g + rr * 8;
                float2 v = make_float2(acc[mi][ni][rr * 2] + bias.x,
                                       acc[mi][ni][rr * 2 + 1] + bias.y);
                *(float2*)(out + (size_t)row * 512 + col) = v;
            }
        }
}

// ---------------------------------------------------------------------------
extern "C" void kernel_launch(void* const* d_in, const int* in_sizes, int n_in,
                              void* d_out, int out_size)
{
    (void)in_sizes; (void)n_in; (void)out_size;
    const float* x  = (const float*)d_in[0];
    const float* Wk = (const float*)d_in[1];
    const float* Wq = (const float*)d_in[2];
    const float* Wv = (const float*)d_in[3];
    const float* Wc = (const float*)d_in[4];
    const float* bc = (const float*)d_in[5];
    float* out = (float*)d_out;

    dim3 blk(256);

    proj_kernel<<<dim3(32, 32, 3), blk>>>(x, Wq, Wk, Wv);
    scores_kernel<<<dim3(16, 16, 16), blk>>>();
    softmax_kernel<<<dim3(32768), blk>>>();
    pv_kernel<<<dim3(4, 16, 16), blk>>>();
    final_kernel<<<dim3(4, 32), blk>>>(Wc, bc, out);
}

// round 9
// speedup vs baseline: 1.2703x; 1.0824x over previous
#include <cuda_runtime.h>
#include <cstdint>

// ---------------------------------------------------------------------------
// MultiHeadAttention b=2,t=2048,e=512,h=8
// Round 6: TF32 mma.sync, block 128x128 / warp 64x32 (2 CTA/SM), double-
// buffered smem, ONE barrier per k-tile, fragment loads via ldmatrix.x4
// (48 LDS.32 -> 12 LDSM per warp-ktile).
// ---------------------------------------------------------------------------

#define NEG_INF (-1e30f)
#define SCALE 0.044194173824159216f   // 1/sqrt(512)
#define SSTR 20                       // smem row stride (words), conflict-free

#define T_WORDS (128 * SSTR)          // one A or B stage

static __device__ float g_q[16 * 2048 * 512];
static __device__ float g_k[16 * 2048 * 512];
static __device__ float g_v[16 * 2048 * 512];
static __device__ float g_p[16u * 2048 * 2048];
static __device__ float g_att[16 * 2048 * 512];

__device__ __forceinline__ unsigned f2tf(float x) {
    unsigned r; asm("cvt.rna.tf32.f32 %0, %1;" : "=r"(r) : "f"(x)); return r;
}
__device__ __forceinline__ uint4 f4tf(float4 v) {
    return make_uint4(f2tf(v.x), f2tf(v.y), f2tf(v.z), f2tf(v.w));
}
__device__ __forceinline__ void mma8(float* d, const unsigned* a, const unsigned* b) {
    asm volatile("mma.sync.aligned.m16n8k8.row.col.f32.tf32.tf32.f32 "
                 "{%0,%1,%2,%3}, {%4,%5,%6,%7}, {%8,%9}, {%0,%1,%2,%3};"
                 : "+f"(d[0]), "+f"(d[1]), "+f"(d[2]), "+f"(d[3])
                 : "r"(a[0]), "r"(a[1]), "r"(a[2]), "r"(a[3]),
                   "r"(b[0]), "r"(b[1]));
}
#define LDSM4(r0, r1, r2, r3, addr) \
    asm volatile("ldmatrix.sync.aligned.m8n8.x4.shared.b16 {%0,%1,%2,%3}, [%4];" \
                 : "=r"(r0), "=r"(r1), "=r"(r2), "=r"(r3) : "r"(addr))

// One 128x128x16 tile. As/Bs are SMEM byte addresses of [row][k] tiles,
// stride SSTR words. Warp (wm,wn) computes 64x32.
// lrow/lk: per-lane ldmatrix source row / k-offset.
__device__ __forceinline__ void compute_tile(uint32_t As, uint32_t Bs,
                                             float acc[4][4][4],
                                             int wm, int wn, int lrow, int lk)
{
#pragma unroll
    for (int kk = 0; kk < 16; kk += 8) {
        unsigned af[4][4];
#pragma unroll
        for (int mi = 0; mi < 4; mi++) {
            uint32_t a = As + (uint32_t)(((wm * 64 + mi * 16 + lrow) * SSTR) + kk + lk) * 4u;
            LDSM4(af[mi][0], af[mi][1], af[mi][2], af[mi][3], a);
        }
        unsigned bf[4][2];
#pragma unroll
        for (int np = 0; np < 2; np++) {
            uint32_t b = Bs + (uint32_t)(((wn * 32 + np * 16 + lrow) * SSTR) + kk + lk) * 4u;
            unsigned r0, r1, r2, r3;
            LDSM4(r0, r1, r2, r3, b);
            bf[2 * np][0] = r0; bf[2 * np + 1][0] = r1;
            bf[2 * np][1] = r2; bf[2 * np + 1][1] = r3;
        }
#pragma unroll
        for (int mi = 0; mi < 4; mi++)
#pragma unroll
            for (int ni = 0; ni < 4; ni++)
                mma8(acc[mi][ni], af[mi], bf[ni]);
    }
}

#define ACC_INIT float acc[4][4][4]; \
    _Pragma("unroll") for (int i = 0; i < 4; i++) \
    _Pragma("unroll") for (int j = 0; j < 4; j++) \
    _Pragma("unroll") for (int k = 0; k < 4; k++) acc[i][j][k] = 0.f;

#define SMEM_DECL \
    __shared__ __align__(16) unsigned AsB[2 * T_WORDS]; \
    __shared__ __align__(16) unsigned BsB[2 * T_WORDS]; \
    const uint32_t AsAddr = (uint32_t)__cvta_generic_to_shared(AsB); \
    const uint32_t BsAddr = (uint32_t)__cvta_generic_to_shared(BsB);

#define LANE_SETUP \
    const int tid = threadIdx.x; \
    const int w = tid >> 5, lane = tid & 31, g = lane >> 2, tg = lane & 3; \
    const int wm = w >> 2, wn = w & 3; \
    const int lrow = (lane & 7) + ((lane >> 3) & 1) * 8; \
    const int lk = (lane >> 4) * 4; \
    const int ak4 = (tid & 3) * 4;

#define STS_STD(stage) do { \
    unsigned* As_ = AsB + (stage) * T_WORDS; \
    unsigned* Bs_ = BsB + (stage) * T_WORDS; \
    _Pragma("unroll") for (int it = 0; it < 2; it++) { \
        int row = (tid + it * 256) >> 2; \
        *(uint4*)&As_[row * SSTR + ak4] = f4tf(pa[it]); \
        *(uint4*)&Bs_[row * SSTR + ak4] = f4tf(pb[it]); \
    } \
} while (0)

// ---------------------------------------------------------------------------
// fused QKV proj: C = X * W^T, M=N=4096, K=512. grid (32,32,3)
// ---------------------------------------------------------------------------
__global__ __launch_bounds__(256) void proj_kernel(const float* __restrict__ X,
                                                   const float* __restrict__ Wq,
                                                   const float* __restrict__ Wk,
                                                   const float* __restrict__ Wv)
{
    SMEM_DECL
    const int z = blockIdx.z;
    const float* W = (z == 0) ? Wq : (z == 1) ? Wk : Wv;
    float* out = (z == 0) ? g_q : (z == 1) ? g_k : g_v;

    const int m0 = blockIdx.y * 128, n0 = blockIdx.x * 128;
    LANE_SETUP
    ACC_INIT
    float4 pa[2], pb[2];

#define LDG_PROJ(k0) do { \
    _Pragma("unroll") for (int it = 0; it < 2; it++) { \
        int row = (tid + it * 256) >> 2; \
        pa[it] = *(const float4*)(X + (size_t)(m0 + row) * 512 + (k0) + ak4); \
        pb[it] = *(const float4*)(W + (size_t)(n0 + row) * 512 + (k0) + ak4); \
    } \
} while (0)

    LDG_PROJ(0);
    STS_STD(0);
    LDG_PROJ(16);
    __syncthreads();

    const int nt = 32;
    for (int kt = 0; kt < nt; kt++) {
        if (kt + 1 < nt) STS_STD((kt + 1) & 1);
        if (kt + 2 < nt) LDG_PROJ((kt + 2) * 16);
        compute_tile(AsAddr + (kt & 1) * T_WORDS * 4, BsAddr + (kt & 1) * T_WORDS * 4,
                     acc, wm, wn, lrow, lk);
        __syncthreads();
    }

#pragma unroll
    for (int mi = 0; mi < 4; mi++)
#pragma unroll
        for (int ni = 0; ni < 4; ni++) {
            int cbase = n0 + wn * 32 + ni * 8 + 2 * tg;
            int h = cbase >> 9, e = cbase & 511;
#pragma unroll
            for (int rr = 0; rr < 2; rr++) {
                int row = m0 + wm * 64 + mi * 16 + g + rr * 8;
                int bb = row >> 11, t = row & 2047;
                float2 v = make_float2(acc[mi][ni][rr * 2], acc[mi][ni][rr * 2 + 1]);
                *(float2*)(out + (((size_t)(bb * 8 + h) * 2048 + t) << 9) + e) = v;
            }
        }
}

// ---------------------------------------------------------------------------
// scores: S = Q K^T * scale + causal. grid (16,16,16), y reversed.
// ---------------------------------------------------------------------------
__global__ __launch_bounds__(256) void scores_kernel()
{
    SMEM_DECL
    const int z = blockIdx.z;
    const int m0 = (15 - blockIdx.y) * 128, n0 = blockIdx.x * 128;
    if (n0 > m0 + 127) return;

    const float* Q = g_q + (size_t)z * 1048576;
    const float* K = g_k + (size_t)z * 1048576;
    float* P = g_p + (size_t)z * 4194304;

    LANE_SETUP
    ACC_INIT
    float4 pa[2], pb[2];

#define LDG_SC(k0) do { \
    _Pragma("unroll") for (int it = 0; it < 2; it++) { \
        int row = (tid + it * 256) >> 2; \
        pa[it] = *(const float4*)(Q + (size_t)(m0 + row) * 512 + (k0) + ak4); \
        pb[it] = *(const float4*)(K + (size_t)(n0 + row) * 512 + (k0) + ak4); \
    } \
} while (0)

    LDG_SC(0);
    STS_STD(0);
    LDG_SC(16);
    __syncthreads();

    const int nt = 32;
    for (int kt = 0; kt < nt; kt++) {
        if (kt + 1 < nt) STS_STD((kt + 1) & 1);
        if (kt + 2 < nt) LDG_SC((kt + 2) * 16);
        compute_tile(AsAddr + (kt & 1) * T_WORDS * 4, BsAddr + (kt & 1) * T_WORDS * 4,
                     acc, wm, wn, lrow, lk);
        __syncthreads();
    }

#pragma unroll
    for (int mi = 0; mi < 4; mi++)
#pragma unroll
        for (int ni = 0; ni < 4; ni++) {
            int col = n0 + wn * 32 + ni * 8 + 2 * tg;
#pragma unroll
            for (int rr = 0; rr < 2; rr++) {
                int row = m0 + wm * 64 + mi * 16 + g + rr * 8;
                float2 v;
                v.x = (col <= row) ? acc[mi][ni][rr * 2] * SCALE : NEG_INF;
                v.y = (col + 1 <= row) ? acc[mi][ni][rr * 2 + 1] * SCALE : NEG_INF;
                *(float2*)(P + (size_t)row * 2048 + col) = v;
            }
        }
}

// ---------------------------------------------------------------------------
// softmax: one block/row, float4, single read+write.
// ---------------------------------------------------------------------------
__global__ __launch_bounds__(256) void softmax_kernel()
{
    const int row = blockIdx.x;
    const int z = row >> 11;
    const int q = row & 2047;
    float4* P4 = (float4*)(g_p + (size_t)z * 4194304 + (size_t)q * 2048);
    const int end4 = (((q >> 7) + 1) << 7) >> 2;

    const int tid = threadIdx.x;
    const int lane = tid & 31, wid = tid >> 5;
    __shared__ float red[8];

    float4 vals[2];
    float m = -3.4e38f;
#pragma unroll
    for (int it = 0; it < 2; it++) {
        int c = tid + it * 256;
        if (c < end4) {
            float4 v = P4[c];
            vals[it] = v;
            m = fmaxf(m, fmaxf(fmaxf(v.x, v.y), fmaxf(v.z, v.w)));
        }
    }
#pragma unroll
    for (int s = 16; s > 0; s >>= 1) m = fmaxf(m, __shfl_xor_sync(~0u, m, s));
    if (lane == 0) red[wid] = m;
    __syncthreads();
    m = red[0];
#pragma unroll
    for (int i = 1; i < 8; i++) m = fmaxf(m, red[i]);

    float sum = 0.f;
#pragma unroll
    for (int it = 0; it < 2; it++) {
        int c = tid + it * 256;
        if (c < end4) {
            float4 v = vals[it];
            v.x = expf(v.x - m); v.y = expf(v.y - m);
            v.z = expf(v.z - m); v.w = expf(v.w - m);
            vals[it] = v;
            sum += v.x + v.y + v.z + v.w;
        }
    }
#pragma unroll
    for (int s = 16; s > 0; s >>= 1) sum += __shfl_xor_sync(~0u, sum, s);
    __syncthreads();
    if (lane == 0) red[wid] = sum;
    __syncthreads();
    sum = 0.f;
#pragma unroll
    for (int i = 0; i < 8; i++) sum += red[i];
    const float inv = 1.f / sum;

#pragma unroll
    for (int it = 0; it < 2; it++) {
        int c = tid + it * 256;
        if (c < end4) {
            float4 v = vals[it];
            v.x *= inv; v.y *= inv; v.z *= inv; v.w *= inv;
            P4[c] = v;
        }
    }
}

// ---------------------------------------------------------------------------
// pv: O = P @ V, M=2048, N=512, K=(by+1)*128. grid (4,16,16), y reversed.
// ---------------------------------------------------------------------------
__global__ __launch_bounds__(256) void pv_kernel()
{
    SMEM_DECL
    const int z = blockIdx.z;
    const int by = 15 - blockIdx.y;
    const int m0 = by * 128, n0 = blockIdx.x * 128;
    const int nt = (by + 1) * 8;

    const float* P = g_p + (size_t)z * 4194304;
    const float* V = g_v + (size_t)z * 1048576;
    float* O = g_att + (size_t)z * 1048576;

    LANE_SETUP
    const int bkr = tid & 15;
    ACC_INIT
    float4 pa[2], pb[2];

#define LDG_PV(k0) do { \
    _Pragma("unroll") for (int it = 0; it < 2; it++) { \
        int l = tid + it * 256; \
        int arow = l >> 2; \
        pa[it] = *(const float4*)(P + (size_t)(m0 + arow) * 2048 + (k0) + ak4); \
        int n4 = l >> 4; \
        pb[it] = *(const float4*)(V + (size_t)((k0) + bkr) * 512 + n0 + n4 * 4); \
    } \
} while (0)

#define STS_PV(stage) do { \
    unsigned* As_ = AsB + (stage) * T_WORDS; \
    unsigned* Bs_ = BsB + (stage) * T_WORDS; \
    _Pragma("unroll") for (int it = 0; it < 2; it++) { \
        int l = tid + it * 256; \
        int arow = l >> 2; \
        *(uint4*)&As_[arow * SSTR + ak4] = f4tf(pa[it]); \
        int nb = (l >> 4) * 4; \
        Bs_[(nb + 0) * SSTR + bkr] = f2tf(pb[it].x); \
        Bs_[(nb + 1) * SSTR + bkr] = f2tf(pb[it].y); \
        Bs_[(nb + 2) * SSTR + bkr] = f2tf(pb[it].z); \
        Bs_[(nb + 3) * SSTR + bkr] = f2tf(pb[it].w); \
    } \
} while (0)

    LDG_PV(0);
    STS_PV(0);
    if (nt > 1) LDG_PV(16);
    __syncthreads();

    for (int kt = 0; kt < nt; kt++) {
        if (kt + 1 < nt) STS_PV((kt + 1) & 1);
        if (kt + 2 < nt) LDG_PV((kt + 2) * 16);
        compute_tile(AsAddr + (kt & 1) * T_WORDS * 4, BsAddr + (kt & 1) * T_WORDS * 4,
                     acc, wm, wn, lrow, lk);
        __syncthreads();
    }

#pragma unroll
    for (int mi = 0; mi < 4; mi++)
#pragma unroll
        for (int ni = 0; ni < 4; ni++) {
            int col = n0 + wn * 32 + ni * 8 + 2 * tg;
#pragma unroll
            for (int rr = 0; rr < 2; rr++) {
                int row = m0 + wm * 64 + mi * 16 + g + rr * 8;
                float2 v = make_float2(acc[mi][ni][rr * 2], acc[mi][ni][rr * 2 + 1]);
                *(float2*)(O + (size_t)row * 512 + col) = v;
            }
        }
}

// ---------------------------------------------------------------------------
// final: out = concat(att) @ Wc^T + bc, M=4096, N=512, K=4096. grid (4,32)
// ---------------------------------------------------------------------------
__global__ __launch_bounds__(256) void final_kernel(const float* __restrict__ Wc,
                                                    const float* __restrict__ bc,
                                                    float* __restrict__ out)
{
    SMEM_DECL
    const int m0 = blockIdx.y * 128, n0 = blockIdx.x * 128;
    LANE_SETUP
    ACC_INIT
    float4 pa[2], pb[2];

#define LDG_FIN(k0) do { \
    _Pragma("unroll") for (int it = 0; it < 2; it++) { \
        int row = (tid + it * 256) >> 2; \
        int gi = m0 + row, bb = gi >> 11, t = gi & 2047; \
        int k = (k0) + ak4, h = k >> 9, e = k & 511; \
        pa[it] = *(const float4*)(g_att + (((size_t)(bb * 8 + h) * 2048 + t) << 9) + e); \
        pb[it] = *(const float4*)(Wc + (size_t)(n0 + row) * 4096 + k); \
    } \
} while (0)

    LDG_FIN(0);
    STS_STD(0);
    LDG_FIN(16);
    __syncthreads();

    const int nt = 256;
    for (int kt = 0; kt < nt; kt++) {
        if (kt + 1 < nt) STS_STD((kt + 1) & 1);
        if (kt + 2 < nt) LDG_FIN((kt + 2) * 16);
        compute_tile(AsAddr + (kt & 1) * T_WORDS * 4, BsAddr + (kt & 1) * T_WORDS * 4,
                     acc, wm, wn, lrow, lk);
        __syncthreads();
    }

#pragma unroll
    for (int mi = 0; mi < 4; mi++)
#pragma unroll
        for (int ni = 0; ni < 4; ni++) {
            int col = n0 + wn * 32 + ni * 8 + 2 * tg;
            float2 bias = *(const float2*)(bc + col);
#pragma unroll
            for (int rr = 0; rr < 2; rr++) {
                int row = m0 + wm * 64 + mi * 16 + g + rr * 8;
                float2 v = make_float2(acc[mi][ni][rr * 2] + bias.x,
                                       acc[mi][ni][rr * 2 + 1] + bias.y);
                *(float2*)(out + (size_t)row * 512 + col) = v;
            }
        }
}

// ---------------------------------------------------------------------------
extern "C" void kernel_launch(void* const* d_in, const int* in_sizes, int n_in,
                              void* d_out, int out_size)
{
    (void)in_sizes; (void)n_in; (void)out_size;
    const float* x  = (const float*)d_in[0];
    const float* Wk = (const float*)d_in[1];
    const float* Wq = (const float*)d_in[2];
    const float* Wv = (const float*)d_in[3];
    const float* Wc = (const float*)d_in[4];
    const float* bc = (const float*)d_in[5];
    float* out = (float*)d_out;

    dim3 blk(256);

    proj_kernel<<<dim3(32, 32, 3), blk>>>(x, Wq, Wk, Wv);
    scores_kernel<<<dim3(16, 16, 16), blk>>>();
    softmax_kernel<<<dim3(32768), blk>>>();
    pv_kernel<<<dim3(4, 16, 16), blk>>>();
    final_kernel<<<dim3(4, 32), blk>>>(Wc, bc, out);
}

// round 12
// speedup vs baseline: 1.3613x; 1.0716x over previous
#include <cuda_runtime.h>
#include <cstdint>

// ---------------------------------------------------------------------------
// MultiHeadAttention b=2,t=2048,e=512,h=8
// Round 7: TF32 mma.sync, 128x128 block / 64x32 warp, double-buffered smem,
// ldmatrix fragment loads. Scratch buffers hold PRE-CONVERTED tf32 bits
// (q,k,att,p-after-softmax) and V is stored TRANSPOSED [head][e][t] at proj
// time -> all consumer smem fills are raw uint4 copies (no cvt, no scalar
// transpose STS in mainloops). Numerics identical to round 6.
// ---------------------------------------------------------------------------

#define NEG_INF (-1e30f)
#define SCALE 0.044194173824159216f   // 1/sqrt(512)
#define SSTR 20                       // smem row stride (words), conflict-free

#define T_WORDS (128 * SSTR)          // one A or B stage

static __device__ unsigned g_q[16 * 2048 * 512];      // tf32 bits (b*h, t, e)
static __device__ unsigned g_k[16 * 2048 * 512];      // tf32 bits
static __device__ unsigned g_vT[16 * 512 * 2048];     // tf32 bits (b*h, e, t)
static __device__ float    g_p[16u * 2048 * 2048];    // fp32 scores -> tf32 probs
static __device__ unsigned g_att[16 * 2048 * 512];    // tf32 bits (b,h,t,e)

__device__ __forceinline__ unsigned f2tf(float x) {
    unsigned r; asm("cvt.rna.tf32.f32 %0, %1;" : "=r"(r) : "f"(x)); return r;
}
__device__ __forceinline__ uint4 f4tf(float4 v) {
    return make_uint4(f2tf(v.x), f2tf(v.y), f2tf(v.z), f2tf(v.w));
}
__device__ __forceinline__ void mma8(float* d, const unsigned* a, const unsigned* b) {
    asm volatile("mma.sync.aligned.m16n8k8.row.col.f32.tf32.tf32.f32 "
                 "{%0,%1,%2,%3}, {%4,%5,%6,%7}, {%8,%9}, {%0,%1,%2,%3};"
                 : "+f"(d[0]), "+f"(d[1]), "+f"(d[2]), "+f"(d[3])
                 : "r"(a[0]), "r"(a[1]), "r"(a[2]), "r"(a[3]),
                   "r"(b[0]), "r"(b[1]));
}
#define LDSM4(r0, r1, r2, r3, addr) \
    asm volatile("ldmatrix.sync.aligned.m8n8.x4.shared.b16 {%0,%1,%2,%3}, [%4];" \
                 : "=r"(r0), "=r"(r1), "=r"(r2), "=r"(r3) : "r"(addr))

__device__ __forceinline__ void compute_tile(uint32_t As, uint32_t Bs,
                                             float acc[4][4][4],
                                             int wm, int wn, int lrow, int lk)
{
#pragma unroll
    for (int kk = 0; kk < 16; kk += 8) {
        unsigned af[4][4];
#pragma unroll
        for (int mi = 0; mi < 4; mi++) {
            uint32_t a = As + (uint32_t)(((wm * 64 + mi * 16 + lrow) * SSTR) + kk + lk) * 4u;
            LDSM4(af[mi][0], af[mi][1], af[mi][2], af[mi][3], a);
        }
        unsigned bf[4][2];
#pragma unroll
        for (int np = 0; np < 2; np++) {
            uint32_t b = Bs + (uint32_t)(((wn * 32 + np * 16 + lrow) * SSTR) + kk + lk) * 4u;
            unsigned r0, r1, r2, r3;
            LDSM4(r0, r1, r2, r3, b);
            bf[2 * np][0] = r0; bf[2 * np + 1][0] = r1;
            bf[2 * np][1] = r2; bf[2 * np + 1][1] = r3;
        }
#pragma unroll
        for (int mi = 0; mi < 4; mi++)
#pragma unroll
            for (int ni = 0; ni < 4; ni++)
                mma8(acc[mi][ni], af[mi], bf[ni]);
    }
}

#define ACC_INIT float acc[4][4][4]; \
    _Pragma("unroll") for (int i = 0; i < 4; i++) \
    _Pragma("unroll") for (int j = 0; j < 4; j++) \
    _Pragma("unroll") for (int k = 0; k < 4; k++) acc[i][j][k] = 0.f;

#define SMEM_DECL \
    __shared__ __align__(16) unsigned AsB[2 * T_WORDS]; \
    __shared__ __align__(16) unsigned BsB[2 * T_WORDS]; \
    const uint32_t AsAddr = (uint32_t)__cvta_generic_to_shared(AsB); \
    const uint32_t BsAddr = (uint32_t)__cvta_generic_to_shared(BsB);

#define LANE_SETUP \
    const int tid = threadIdx.x; \
    const int w = tid >> 5, lane = tid & 31, g = lane >> 2, tg = lane & 3; \
    const int wm = w >> 2, wn = w & 3; \
    const int lrow = (lane & 7) + ((lane >> 3) & 1) * 8; \
    const int lk = (lane >> 4) * 4; \
    const int ak4 = (tid & 3) * 4;

#define STS_RAW(stage) do { \
    unsigned* As_ = AsB + (stage) * T_WORDS; \
    unsigned* Bs_ = BsB + (stage) * T_WORDS; \
    _Pragma("unroll") for (int it = 0; it < 2; it++) { \
        int row = (tid + it * 256) >> 2; \
        *(uint4*)&As_[row * SSTR + ak4] = ua[it]; \
        *(uint4*)&Bs_[row * SSTR + ak4] = ub[it]; \
    } \
} while (0)

// ---------------------------------------------------------------------------
// fused QKV proj: C = X * W^T, M=N=4096, K=512. grid (32,32,3).
// ---------------------------------------------------------------------------
__global__ __launch_bounds__(256) void proj_kernel(const float* __restrict__ X,
                                                   const float* __restrict__ Wq,
                                                   const float* __restrict__ Wk,
                                                   const float* __restrict__ Wv)
{
    SMEM_DECL
    const int z = blockIdx.z;
    const float* W = (z == 0) ? Wq : (z == 1) ? Wk : Wv;

    const int m0 = blockIdx.y * 128, n0 = blockIdx.x * 128;
    LANE_SETUP
    ACC_INIT
    float4 pa[2], pb[2];

#define LDG_PROJ(k0) do { \
    _Pragma("unroll") for (int it = 0; it < 2; it++) { \
        int row = (tid + it * 256) >> 2; \
        pa[it] = *(const float4*)(X + (size_t)(m0 + row) * 512 + (k0) + ak4); \
        pb[it] = *(const float4*)(W + (size_t)(n0 + row) * 512 + (k0) + ak4); \
    } \
} while (0)

#define STS_CVT(stage) do { \
    unsigned* As_ = AsB + (stage) * T_WORDS; \
    unsigned* Bs_ = BsB + (stage) * T_WORDS; \
    _Pragma("unroll") for (int it = 0; it < 2; it++) { \
        int row = (tid + it * 256) >> 2; \
        *(uint4*)&As_[row * SSTR + ak4] = f4tf(pa[it]); \
        *(uint4*)&Bs_[row * SSTR + ak4] = f4tf(pb[it]); \
    } \
} while (0)

    LDG_PROJ(0);
    STS_CVT(0);
    LDG_PROJ(16);
    __syncthreads();

    const int nt = 32;
    for (int kt = 0; kt < nt; kt++) {
        if (kt + 1 < nt) STS_CVT((kt + 1) & 1);
        if (kt + 2 < nt) LDG_PROJ((kt + 2) * 16);
        compute_tile(AsAddr + (kt & 1) * T_WORDS * 4, BsAddr + (kt & 1) * T_WORDS * 4,
                     acc, wm, wn, lrow, lk);
        __syncthreads();
    }

    if (z < 2) {
        unsigned* out = (z == 0) ? g_q : g_k;
#pragma unroll
        for (int mi = 0; mi < 4; mi++)
#pragma unroll
            for (int ni = 0; ni < 4; ni++) {
                int cbase = n0 + wn * 32 + ni * 8 + 2 * tg;
                int h = cbase >> 9, e = cbase & 511;
#pragma unroll
                for (int rr = 0; rr < 2; rr++) {
                    int row = m0 + wm * 64 + mi * 16 + g + rr * 8;
                    int bb = row >> 11, t = row & 2047;
                    uint2 v = make_uint2(f2tf(acc[mi][ni][rr * 2]),
                                         f2tf(acc[mi][ni][rr * 2 + 1]));
                    *(uint2*)(out + (((size_t)(bb * 8 + h) * 2048 + t) << 9) + e) = v;
                }
            }
    } else {
#pragma unroll
        for (int mi = 0; mi < 4; mi++)
#pragma unroll
            for (int ni = 0; ni < 4; ni++) {
                int cbase = n0 + wn * 32 + ni * 8 + 2 * tg;
                int h = cbase >> 9, e = cbase & 511;
#pragma unroll
                for (int rr = 0; rr < 2; rr++) {
                    int row = m0 + wm * 64 + mi * 16 + g + rr * 8;
                    int bb = row >> 11, t = row & 2047;
                    size_t base = ((size_t)(bb * 8 + h) * 512 + e) * 2048 + t;
                    g_vT[base]        = f2tf(acc[mi][ni][rr * 2]);
                    g_vT[base + 2048] = f2tf(acc[mi][ni][rr * 2 + 1]);
                }
            }
    }
}

// ---------------------------------------------------------------------------
// scores: S = Q K^T * scale + causal (fp32 out). grid (16,16,16), y reversed.
// ---------------------------------------------------------------------------
__global__ __launch_bounds__(256) void scores_kernel()
{
    SMEM_DECL
    const int z = blockIdx.z;
    const int m0 = (15 - blockIdx.y) * 128, n0 = blockIdx.x * 128;
    if (n0 > m0 + 127) return;

    const unsigned* Q = g_q + (size_t)z * 1048576;
    const unsigned* K = g_k + (size_t)z * 1048576;
    float* P = g_p + (size_t)z * 4194304;

    LANE_SETUP
    ACC_INIT
    uint4 ua[2], ub[2];

#define LDG_SC(k0) do { \
    _Pragma("unroll") for (int it = 0; it < 2; it++) { \
        int row = (tid + it * 256) >> 2; \
        ua[it] = *(const uint4*)(Q + (size_t)(m0 + row) * 512 + (k0) + ak4); \
        ub[it] = *(const uint4*)(K + (size_t)(n0 + row) * 512 + (k0) + ak4); \
    } \
} while (0)

    LDG_SC(0);
    STS_RAW(0);
    LDG_SC(16);
    __syncthreads();

    const int nt = 32;
    for (int kt = 0; kt < nt; kt++) {
        if (kt + 1 < nt) STS_RAW((kt + 1) & 1);
        if (kt + 2 < nt) LDG_SC((kt + 2) * 16);
        compute_tile(AsAddr + (kt & 1) * T_WORDS * 4, BsAddr + (kt & 1) * T_WORDS * 4,
                     acc, wm, wn, lrow, lk);
        __syncthreads();
    }

#pragma unroll
    for (int mi = 0; mi < 4; mi++)
#pragma unroll
        for (int ni = 0; ni < 4; ni++) {
            int col = n0 + wn * 32 + ni * 8 + 2 * tg;
#pragma unroll
            for (int rr = 0; rr < 2; rr++) {
                int row = m0 + wm * 64 + mi * 16 + g + rr * 8;
                float2 v;
                v.x = (col <= row) ? acc[mi][ni][rr * 2] * SCALE : NEG_INF;
                v.y = (col + 1 <= row) ? acc[mi][ni][rr * 2 + 1] * SCALE : NEG_INF;
                *(float2*)(P + (size_t)row * 2048 + col) = v;
            }
        }
}

// ---------------------------------------------------------------------------
// softmax: fp32 in, tf32-bits out.
// ---------------------------------------------------------------------------
__global__ __launch_bounds__(256) void softmax_kernel()
{
    const int row = blockIdx.x;
    const int z = row >> 11;
    const int q = row & 2047;
    float4* P4 = (float4*)(g_p + (size_t)z * 4194304 + (size_t)q * 2048);
    const int end4 = (((q >> 7) + 1) << 7) >> 2;

    const int tid = threadIdx.x;
    const int lane = tid & 31, wid = tid >> 5;
    __shared__ float red[8];

    float4 vals[2];
    float m = -3.4e38f;
#pragma unroll
    for (int it = 0; it < 2; it++) {
        int c = tid + it * 256;
        if (c < end4) {
            float4 v = P4[c];
            vals[it] = v;
            m = fmaxf(m, fmaxf(fmaxf(v.x, v.y), fmaxf(v.z, v.w)));
        }
    }
#pragma unroll
    for (int s = 16; s > 0; s >>= 1) m = fmaxf(m, __shfl_xor_sync(~0u, m, s));
    if (lane == 0) red[wid] = m;
    __syncthreads();
    m = red[0];
#pragma unroll
    for (int i = 1; i < 8; i++) m = fmaxf(m, red[i]);

    float sum = 0.f;
#pragma unroll
    for (int it = 0; it < 2; it++) {
        int c = tid + it * 256;
        if (c < end4) {
            float4 v = vals[it];
            v.x = expf(v.x - m); v.y = expf(v.y - m);
            v.z = expf(v.z - m); v.w = expf(v.w - m);
            vals[it] = v;
            sum += v.x + v.y + v.z + v.w;
        }
    }
#pragma unroll
    for (int s = 16; s > 0; s >>= 1) sum += __shfl_xor_sync(~0u, sum, s);
    __syncthreads();
    if (lane == 0) red[wid] = sum;
    __syncthreads();
    sum = 0.f;
#pragma unroll
    for (int i = 0; i < 8; i++) sum += red[i];
    const float inv = 1.f / sum;

#pragma unroll
    for (int it = 0; it < 2; it++) {
        int c = tid + it * 256;
        if (c < end4) {
            float4 v = vals[it];
            v.x = __uint_as_float(f2tf(v.x * inv));
            v.y = __uint_as_float(f2tf(v.y * inv));
            v.z = __uint_as_float(f2tf(v.z * inv));
            v.w = __uint_as_float(f2tf(v.w * inv));
            P4[c] = v;
        }
    }
}

// ---------------------------------------------------------------------------
// pv: O = P @ V (both pre-tf32, V pre-transposed). grid (4,16,16), y reversed.
// ---------------------------------------------------------------------------
__global__ __launch_bounds__(256) void pv_kernel()
{
    SMEM_DECL
    const int z = blockIdx.z;
    const int by = 15 - blockIdx.y;
    const int m0 = by * 128, n0 = blockIdx.x * 128;
    const int nt = (by + 1) * 8;

    const unsigned* P = (const unsigned*)(g_p + (size_t)z * 4194304);
    const unsigned* VT = g_vT + (size_t)z * 1048576;
    unsigned* O = g_att + (size_t)z * 1048576;

    LANE_SETUP
    ACC_INIT
    uint4 ua[2], ub[2];

#define LDG_PV(k0) do { \
    _Pragma("unroll") for (int it = 0; it < 2; it++) { \
        int row = (tid + it * 256) >> 2; \
        ua[it] = *(const uint4*)(P + (size_t)(m0 + row) * 2048 + (k0) + ak4); \
        ub[it] = *(const uint4*)(VT + (size_t)(n0 + row) * 2048 + (k0) + ak4); \
    } \
} while (0)

    LDG_PV(0);
    STS_RAW(0);
    if (nt > 1) LDG_PV(16);
    __syncthreads();

    for (int kt = 0; kt < nt; kt++) {
        if (kt + 1 < nt) STS_RAW((kt + 1) & 1);
        if (kt + 2 < nt) LDG_PV((kt + 2) * 16);
        compute_tile(AsAddr + (kt & 1) * T_WORDS * 4, BsAddr + (kt & 1) * T_WORDS * 4,
                     acc, wm, wn, lrow, lk);
        __syncthreads();
    }

#pragma unroll
    for (int mi = 0; mi < 4; mi++)
#pragma unroll
        for (int ni = 0; ni < 4; ni++) {
            int col = n0 + wn * 32 + ni * 8 + 2 * tg;
#pragma unroll
            for (int rr = 0; rr < 2; rr++) {
                int row = m0 + wm * 64 + mi * 16 + g + rr * 8;
                uint2 v = make_uint2(f2tf(acc[mi][ni][rr * 2]),
                                     f2tf(acc[mi][ni][rr * 2 + 1]));
                *(uint2*)(O + (size_t)row * 512 + col) = v;
            }
        }
}

// ---------------------------------------------------------------------------
// final: out = concat(att) @ Wc^T + bc. grid (4,32).
// ---------------------------------------------------------------------------
__global__ __launch_bounds__(256) void final_kernel(const float* __restrict__ Wc,
                                                    const float* __restrict__ bc,
                                                    float* __restrict__ out)
{
    SMEM_DECL
    const int m0 = blockIdx.y * 128, n0 = blockIdx.x * 128;
    LANE_SETUP
    ACC_INIT
    uint4 ua[2];
    float4 pb[2];

#define LDG_FIN(k0) do { \
    _Pragma("unroll") for (int it = 0; it < 2; it++) { \
        int row = (tid + it * 256) >> 2; \
        int gi = m0 + row, bb = gi >> 11, t = gi & 2047; \
        int k = (k0) + ak4, h = k >> 9, e = k & 511; \
        ua[it] = *(const uint4*)(g_att + (((size_t)(bb * 8 + h) * 2048 + t) << 9) + e); \
        pb[it] = *(const float4*)(Wc + (size_t)(n0 + row) * 4096 + k); \
    } \
} while (0)

#define STS_FIN(stage) do { \
    unsigned* As_ = AsB + (stage) * T_WORDS; \
    unsigned* Bs_ = BsB + (stage) * T_WORDS; \
    _Pragma("unroll") for (int it = 0; it < 2; it++) { \
        int row = (tid + it * 256) >> 2; \
        *(uint4*)&As_[row * SSTR + ak4] = ua[it]; \
        *(uint4*)&Bs_[row * SSTR + ak4] = f4tf(pb[it]); \
    } \
} while (0)

    LDG_FIN(0);
    STS_FIN(0);
    LDG_FIN(16);
    __syncthreads();

    const int nt = 256;
    for (int kt = 0; kt < nt; kt++) {
        if (kt + 1 < nt) STS_FIN((kt + 1) & 1);
        if (kt + 2 < nt) LDG_FIN((kt + 2) * 16);
        compute_tile(AsAddr + (kt & 1) * T_WORDS * 4, BsAddr + (kt & 1) * T_WORDS * 4,
                     acc, wm, wn, lrow, lk);
        __syncthreads();
    }

#pragma unroll
    for (int mi = 0; mi < 4; mi++)
#pragma unroll
        for (int ni = 0; ni < 4; ni++) {
            int col = n0 + wn * 32 + ni * 8 + 2 * tg;
            float2 bias = *(const float2*)(bc + col);
#pragma unroll
            for (int rr = 0; rr < 2; rr++) {
                int row = m0 + wm * 64 + mi * 16 + g + rr * 8;
                float2 v = make_float2(acc[mi][ni][rr * 2] + bias.x,
                                       acc[mi][ni][rr * 2 + 1] + bias.y);
                *(float2*)(out + (size_t)row * 512 + col) = v;
            }
        }
}

// ---------------------------------------------------------------------------
extern "C" void kernel_launch(void* const* d_in, const int* in_sizes, int n_in,
                              void* d_out, int out_size)
{
    (void)in_sizes; (void)n_in; (void)out_size;
    const float* x  = (const float*)d_in[0];
    const float* Wk = (const float*)d_in[1];
    const float* Wq = (const float*)d_in[2];
    const float* Wv = (const float*)d_in[3];
    const float* Wc = (const float*)d_in[4];
    const float* bc = (const float*)d_in[5];
    float* out = (float*)d_out;

    dim3 blk(256);

    proj_kernel<<<dim3(32, 32, 3), blk>>>(x, Wq, Wk, Wv);
    scores_kernel<<<dim3(16, 16, 16), blk>>>();
    softmax_kernel<<<dim3(32768), blk>>>();
    pv_kernel<<<dim3(4, 16, 16), blk>>>();
    final_kernel<<<dim3(4, 32), blk>>>(Wc, bc, out);
}

// round 14
// speedup vs baseline: 1.3822x; 1.0154x over previous
#include <cuda_runtime.h>
#include <cstdint>

// ---------------------------------------------------------------------------
// MultiHeadAttention b=2,t=2048,e=512,h=8
// Round 8: TF32 mma.sync, 128x128 block / 64x32 warp, ldmatrix fragments.
// ALL GEMM operands pre-converted to tf32 bits in scratch; mainloop fills are
// cp.async.cg (LDGSTS) into a 3-stage pipeline, one barrier per k-tile.
// ---------------------------------------------------------------------------

#define NEG_INF (-1e30f)
#define SCALE 0.044194173824159216f   // 1/sqrt(512)
#define SSTR 20                       // smem row stride (words), conflict-free
#define T_WORDS (128 * SSTR)          // one A or B stage (words)
#define STAGES 3
#define SMEM_BYTES (2 * STAGES * T_WORDS * 4)   // 61440

// tf32-bit scratch
static __device__ unsigned g_xtf [4096 * 512];
static __device__ unsigned g_wqtf[4096 * 512];
static __device__ unsigned g_wktf[4096 * 512];
static __device__ unsigned g_wvtf[4096 * 512];
static __device__ unsigned g_wctf[512 * 4096];
static __device__ unsigned g_q  [16 * 2048 * 512];    // (b*h, t, e)
static __device__ unsigned g_k  [16 * 2048 * 512];
static __device__ unsigned g_vT [16 * 512 * 2048];    // (b*h, e, t)
static __device__ float    g_p  [16u * 2048 * 2048];  // fp32 scores -> tf32 probs
static __device__ unsigned g_att[16 * 2048 * 512];    // (b,h,t,e)

__device__ __forceinline__ unsigned f2tf(float x) {
    unsigned r; asm("cvt.rna.tf32.f32 %0, %1;" : "=r"(r) : "f"(x)); return r;
}
__device__ __forceinline__ uint4 f4tf(float4 v) {
    return make_uint4(f2tf(v.x), f2tf(v.y), f2tf(v.z), f2tf(v.w));
}
__device__ __forceinline__ void mma8(float* d, const unsigned* a, const unsigned* b) {
    asm volatile("mma.sync.aligned.m16n8k8.row.col.f32.tf32.tf32.f32 "
                 "{%0,%1,%2,%3}, {%4,%5,%6,%7}, {%8,%9}, {%0,%1,%2,%3};"
                 : "+f"(d[0]), "+f"(d[1]), "+f"(d[2]), "+f"(d[3])
                 : "r"(a[0]), "r"(a[1]), "r"(a[2]), "r"(a[3]),
                   "r"(b[0]), "r"(b[1]));
}
#define LDSM4(r0, r1, r2, r3, addr) \
    asm volatile("ldmatrix.sync.aligned.m8n8.x4.shared.b16 {%0,%1,%2,%3}, [%4];" \
                 : "=r"(r0), "=r"(r1), "=r"(r2), "=r"(r3) : "r"(addr))
#define CP16(dst, src) \
    asm volatile("cp.async.cg.shared.global [%0], [%1], 16;" :: "r"(dst), "l"(src))
#define CPCOMMIT() asm volatile("cp.async.commit_group;")
#define CPWAIT1()  asm volatile("cp.async.wait_group 1;")

__device__ __forceinline__ void compute_tile(uint32_t As, uint32_t Bs,
                                             float acc[4][4][4],
                                             int wm, int wn, int lrow, int lk)
{
#pragma unroll
    for (int kk = 0; kk < 16; kk += 8) {
        unsigned af[4][4];
#pragma unroll
        for (int mi = 0; mi < 4; mi++) {
            uint32_t a = As + (uint32_t)(((wm * 64 + mi * 16 + lrow) * SSTR) + kk + lk) * 4u;
            LDSM4(af[mi][0], af[mi][1], af[mi][2], af[mi][3], a);
        }
        unsigned bf[4][2];
#pragma unroll
        for (int np = 0; np < 2; np++) {
            uint32_t b = Bs + (uint32_t)(((wn * 32 + np * 16 + lrow) * SSTR) + kk + lk) * 4u;
            unsigned r0, r1, r2, r3;
            LDSM4(r0, r1, r2, r3, b);
            bf[2 * np][0] = r0; bf[2 * np + 1][0] = r1;
            bf[2 * np][1] = r2; bf[2 * np + 1][1] = r3;
        }
#pragma unroll
        for (int mi = 0; mi < 4; mi++)
#pragma unroll
            for (int ni = 0; ni < 4; ni++)
                mma8(acc[mi][ni], af[mi], bf[ni]);
    }
}

#define ACC_INIT float acc[4][4][4]; \
    _Pragma("unroll") for (int i = 0; i < 4; i++) \
    _Pragma("unroll") for (int j = 0; j < 4; j++) \
    _Pragma("unroll") for (int k = 0; k < 4; k++) acc[i][j][k] = 0.f;

#define SMEM_DECL \
    extern __shared__ unsigned smemraw[]; \
    const uint32_t AsAddr = (uint32_t)__cvta_generic_to_shared(smemraw); \
    const uint32_t BsAddr = AsAddr + STAGES * T_WORDS * 4;

#define LANE_SETUP \
    const int tid = threadIdx.x; \
    const int w = tid >> 5, lane = tid & 31, g = lane >> 2, tg = lane & 3; \
    const int wm = w >> 2, wn = w & 3; \
    const int lrow = (lane & 7) + ((lane >> 3) & 1) * 8; \
    const int lk = (lane >> 4) * 4; \
    const int ak4 = (tid & 3) * 4; \
    const int r0 = tid >> 2, r1 = r0 + 64; \
    const int sA0 = r0 * SSTR + ak4, sA1 = r1 * SSTR + ak4;

// Generic issue for linear-in-k operand pointers (words).
#define ISSUE_LIN(stage, k0, pA0, pA1, pB0, pB1) do { \
    uint32_t ao = AsAddr + (uint32_t)(stage) * (T_WORDS * 4); \
    uint32_t bo = BsAddr + (uint32_t)(stage) * (T_WORDS * 4); \
    CP16(ao + sA0 * 4, (pA0) + (k0)); \
    CP16(ao + sA1 * 4, (pA1) + (k0)); \
    CP16(bo + sA0 * 4, (pB0) + (k0)); \
    CP16(bo + sA1 * 4, (pB1) + (k0)); \
    CPCOMMIT(); \
} while (0)

#define STAGE_ROT(v) v = (v == STAGES - 1) ? 0 : v + 1

// ---------------------------------------------------------------------------
// cvt: convert x, Wq, Wk, Wv, Wc (fp32) -> tf32 bit scratch. 5 x 2M words.
// ---------------------------------------------------------------------------
__global__ __launch_bounds__(256) void cvt_kernel(const float4* __restrict__ x,
                                                  const float4* __restrict__ wq,
                                                  const float4* __restrict__ wk,
                                                  const float4* __restrict__ wv,
                                                  const float4* __restrict__ wc)
{
    int i = blockIdx.x * 256 + threadIdx.x;   // 0 .. 2621439
    int seg = i >> 19, off = i & 524287;
    const float4* src;
    uint4* dst;
    switch (seg) {
        case 0:  src = x;  dst = (uint4*)g_xtf;  break;
        case 1:  src = wq; dst = (uint4*)g_wqtf; break;
        case 2:  src = wk; dst = (uint4*)g_wktf; break;
        case 3:  src = wv; dst = (uint4*)g_wvtf; break;
        default: src = wc; dst = (uint4*)g_wctf; break;
    }
    dst[off] = f4tf(src[off]);
}

// ---------------------------------------------------------------------------
// fused QKV proj: C = X * W^T, M=N=4096, K=512. grid (32,32,3).
// ---------------------------------------------------------------------------
__global__ __launch_bounds__(256) void proj_kernel()
{
    SMEM_DECL
    const int z = blockIdx.z;
    const unsigned* W = (z == 0) ? g_wqtf : (z == 1) ? g_wktf : g_wvtf;

    const int m0 = blockIdx.y * 128, n0 = blockIdx.x * 128;
    LANE_SETUP
    ACC_INIT

    const unsigned* pA0 = g_xtf + (size_t)(m0 + r0) * 512 + ak4;
    const unsigned* pA1 = g_xtf + (size_t)(m0 + r1) * 512 + ak4;
    const unsigned* pB0 = W + (size_t)(n0 + r0) * 512 + ak4;
    const unsigned* pB1 = W + (size_t)(n0 + r1) * 512 + ak4;

    ISSUE_LIN(0, 0, pA0, pA1, pB0, pB1);
    ISSUE_LIN(1, 16, pA0, pA1, pB0, pB1);

    const int nt = 32;
    int st = 0, ist = 2;
    for (int kt = 0; kt < nt; kt++) {
        CPWAIT1();
        __syncthreads();
        if (kt + 2 < nt) ISSUE_LIN(ist, (kt + 2) * 16, pA0, pA1, pB0, pB1);
        compute_tile(AsAddr + st * (T_WORDS * 4), BsAddr + st * (T_WORDS * 4),
                     acc, wm, wn, lrow, lk);
        STAGE_ROT(st); STAGE_ROT(ist);
    }

    if (z < 2) {
        unsigned* out = (z == 0) ? g_q : g_k;
#pragma unroll
        for (int mi = 0; mi < 4; mi++)
#pragma unroll
            for (int ni = 0; ni < 4; ni++) {
                int cbase = n0 + wn * 32 + ni * 8 + 2 * tg;
                int h = cbase >> 9, e = cbase & 511;
#pragma unroll
                for (int rr = 0; rr < 2; rr++) {
                    int row = m0 + wm * 64 + mi * 16 + g + rr * 8;
                    int bb = row >> 11, t = row & 2047;
                    uint2 v = make_uint2(f2tf(acc[mi][ni][rr * 2]),
                                         f2tf(acc[mi][ni][rr * 2 + 1]));
                    *(uint2*)(out + (((size_t)(bb * 8 + h) * 2048 + t) << 9) + e) = v;
                }
            }
    } else {
#pragma unroll
        for (int mi = 0; mi < 4; mi++)
#pragma unroll
            for (int ni = 0; ni < 4; ni++) {
                int cbase = n0 + wn * 32 + ni * 8 + 2 * tg;
                int h = cbase >> 9, e = cbase & 511;
#pragma unroll
                for (int rr = 0; rr < 2; rr++) {
                    int row = m0 + wm * 64 + mi * 16 + g + rr * 8;
                    int bb = row >> 11, t = row & 2047;
                    size_t base = ((size_t)(bb * 8 + h) * 512 + e) * 2048 + t;
                    g_vT[base]        = f2tf(acc[mi][ni][rr * 2]);
                    g_vT[base + 2048] = f2tf(acc[mi][ni][rr * 2 + 1]);
                }
            }
    }
}

// ---------------------------------------------------------------------------
// scores: S = Q K^T * scale + causal (fp32 out). grid (16,16,16), y reversed.
// ---------------------------------------------------------------------------
__global__ __launch_bounds__(256) void scores_kernel()
{
    SMEM_DECL
    const int z = blockIdx.z;
    const int m0 = (15 - blockIdx.y) * 128, n0 = blockIdx.x * 128;
    if (n0 > m0 + 127) return;

    const unsigned* Q = g_q + (size_t)z * 1048576;
    const unsigned* K = g_k + (size_t)z * 1048576;
    float* P = g_p + (size_t)z * 4194304;

    LANE_SETUP
    ACC_INIT

    const unsigned* pA0 = Q + (size_t)(m0 + r0) * 512 + ak4;
    const unsigned* pA1 = Q + (size_t)(m0 + r1) * 512 + ak4;
    const unsigned* pB0 = K + (size_t)(n0 + r0) * 512 + ak4;
    const unsigned* pB1 = K + (size_t)(n0 + r1) * 512 + ak4;

    ISSUE_LIN(0, 0, pA0, pA1, pB0, pB1);
    ISSUE_LIN(1, 16, pA0, pA1, pB0, pB1);

    const int nt = 32;
    int st = 0, ist = 2;
    for (int kt = 0; kt < nt; kt++) {
        CPWAIT1();
        __syncthreads();
        if (kt + 2 < nt) ISSUE_LIN(ist, (kt + 2) * 16, pA0, pA1, pB0, pB1);
        compute_tile(AsAddr + st * (T_WORDS * 4), BsAddr + st * (T_WORDS * 4),
                     acc, wm, wn, lrow, lk);
        STAGE_ROT(st); STAGE_ROT(ist);
    }

#pragma unroll
    for (int mi = 0; mi < 4; mi++)
#pragma unroll
        for (int ni = 0; ni < 4; ni++) {
            int col = n0 + wn * 32 + ni * 8 + 2 * tg;
#pragma unroll
            for (int rr = 0; rr < 2; rr++) {
                int row = m0 + wm * 64 + mi * 16 + g + rr * 8;
                float2 v;
                v.x = (col <= row) ? acc[mi][ni][rr * 2] * SCALE : NEG_INF;
                v.y = (col + 1 <= row) ? acc[mi][ni][rr * 2 + 1] * SCALE : NEG_INF;
                *(float2*)(P + (size_t)row * 2048 + col) = v;
            }
        }
}

// ---------------------------------------------------------------------------
// softmax: fp32 in, tf32-bits out.
// ---------------------------------------------------------------------------
__global__ __launch_bounds__(256) void softmax_kernel()
{
    const int row = blockIdx.x;
    const int z = row >> 11;
    const int q = row & 2047;
    float4* P4 = (float4*)(g_p + (size_t)z * 4194304 + (size_t)q * 2048);
    const int end4 = (((q >> 7) + 1) << 7) >> 2;

    const int tid = threadIdx.x;
    const int lane = tid & 31, wid = tid >> 5;
    __shared__ float red[8];

    float4 vals[2];
    float m = -3.4e38f;
#pragma unroll
    for (int it = 0; it < 2; it++) {
        int c = tid + it * 256;
        if (c < end4) {
            float4 v = P4[c];
            vals[it] = v;
            m = fmaxf(m, fmaxf(fmaxf(v.x, v.y), fmaxf(v.z, v.w)));
        }
    }
#pragma unroll
    for (int s = 16; s > 0; s >>= 1) m = fmaxf(m, __shfl_xor_sync(~0u, m, s));
    if (lane == 0) red[wid] = m;
    __syncthreads();
    m = red[0];
#pragma unroll
    for (int i = 1; i < 8; i++) m = fmaxf(m, red[i]);

    float sum = 0.f;
#pragma unroll
    for (int it = 0; it < 2; it++) {
        int c = tid + it * 256;
        if (c < end4) {
            float4 v = vals[it];
            v.x = expf(v.x - m); v.y = expf(v.y - m);
            v.z = expf(v.z - m); v.w = expf(v.w - m);
            vals[it] = v;
            sum += v.x + v.y + v.z + v.w;
        }
    }
#pragma unroll
    for (int s = 16; s > 0; s >>= 1) sum += __shfl_xor_sync(~0u, sum, s);
    __syncthreads();
    if (lane == 0) red[wid] = sum;
    __syncthreads();
    sum = 0.f;
#pragma unroll
    for (int i = 0; i < 8; i++) sum += red[i];
    const float inv = 1.f / sum;

#pragma unroll
    for (int it = 0; it < 2; it++) {
        int c = tid + it * 256;
        if (c < end4) {
            float4 v = vals[it];
            v.x = __uint_as_float(f2tf(v.x * inv));
            v.y = __uint_as_float(f2tf(v.y * inv));
            v.z = __uint_as_float(f2tf(v.z * inv));
            v.w = __uint_as_float(f2tf(v.w * inv));
            P4[c] = v;
        }
    }
}

// ---------------------------------------------------------------------------
// pv: O = P @ V (pre-tf32, V pre-transposed). grid (4,16,16), y reversed.
// ---------------------------------------------------------------------------
__global__ __launch_bounds__(256) void pv_kernel()
{
    SMEM_DECL
    const int z = blockIdx.z;
    const int by = 15 - blockIdx.y;
    const int m0 = by * 128, n0 = blockIdx.x * 128;
    const int nt = (by + 1) * 8;

    const unsigned* P = (const unsigned*)(g_p + (size_t)z * 4194304);
    const unsigned* VT = g_vT + (size_t)z * 1048576;
    unsigned* O = g_att + (size_t)z * 1048576;

    LANE_SETUP
    ACC_INIT

    const unsigned* pA0 = P + (size_t)(m0 + r0) * 2048 + ak4;
    const unsigned* pA1 = P + (size_t)(m0 + r1) * 2048 + ak4;
    const unsigned* pB0 = VT + (size_t)(n0 + r0) * 2048 + ak4;
    const unsigned* pB1 = VT + (size_t)(n0 + r1) * 2048 + ak4;

    ISSUE_LIN(0, 0, pA0, pA1, pB0, pB1);
    ISSUE_LIN(1, 16, pA0, pA1, pB0, pB1);

    int st = 0, ist = 2;
    for (int kt = 0; kt < nt; kt++) {
        CPWAIT1();
        __syncthreads();
        if (kt + 2 < nt) ISSUE_LIN(ist, (kt + 2) * 16, pA0, pA1, pB0, pB1);
        compute_tile(AsAddr + st * (T_WORDS * 4), BsAddr + st * (T_WORDS * 4),
                     acc, wm, wn, lrow, lk);
        STAGE_ROT(st); STAGE_ROT(ist);
    }

#pragma unroll
    for (int mi = 0; mi < 4; mi++)
#pragma unroll
        for (int ni = 0; ni < 4; ni++) {
            int col = n0 + wn * 32 + ni * 8 + 2 * tg;
#pragma unroll
            for (int rr = 0; rr < 2; rr++) {
                int row = m0 + wm * 64 + mi * 16 + g + rr * 8;
                uint2 v = make_uint2(f2tf(acc[mi][ni][rr * 2]),
                                     f2tf(acc[mi][ni][rr * 2 + 1]));
                *(uint2*)(O + (size_t)row * 512 + col) = v;
            }
        }
}

// ---------------------------------------------------------------------------
// final: out = concat(att) @ Wc^T + bc. grid (4,32).
// ---------------------------------------------------------------------------
__global__ __launch_bounds__(256) void final_kernel(const float* __restrict__ bc,
                                                    float* __restrict__ out)
{
    SMEM_DECL
    const int m0 = blockIdx.y * 128, n0 = blockIdx.x * 128;
    LANE_SETUP
    ACC_INIT

    const int gi0 = m0 + r0, bb0 = gi0 >> 11, t0 = gi0 & 2047;
    const int gi1 = m0 + r1, bb1 = gi1 >> 11, t1 = gi1 & 2047;
    const unsigned* pB0 = g_wctf + (size_t)(n0 + r0) * 4096 + ak4;
    const unsigned* pB1 = g_wctf + (size_t)(n0 + r1) * 4096 + ak4;

#define ISSUE_FIN(stage, kt2) do { \
    int k = (kt2) * 16 + ak4; \
    int h = k >> 9, e = k & 511; \
    const unsigned* a0 = g_att + (((size_t)(bb0 * 8 + h) * 2048 + t0) << 9) + e; \
    const unsigned* a1 = g_att + (((size_t)(bb1 * 8 + h) * 2048 + t1) << 9) + e; \
    uint32_t ao = AsAddr + (uint32_t)(stage) * (T_WORDS * 4); \
    uint32_t bo = BsAddr + (uint32_t)(stage) * (T_WORDS * 4); \
    CP16(ao + sA0 * 4, a0); \
    CP16(ao + sA1 * 4, a1); \
    CP16(bo + sA0 * 4, pB0 + (kt2) * 16); \
    CP16(bo + sA1 * 4, pB1 + (kt2) * 16); \
    CPCOMMIT(); \
} while (0)

    ISSUE_FIN(0, 0);
    ISSUE_FIN(1, 1);

    const int nt = 256;
    int st = 0, ist = 2;
    for (int kt = 0; kt < nt; kt++) {
        CPWAIT1();
        __syncthreads();
        if (kt + 2 < nt) ISSUE_FIN(ist, kt + 2);
        compute_tile(AsAddr + st * (T_WORDS * 4), BsAddr + st * (T_WORDS * 4),
                     acc, wm, wn, lrow, lk);
        STAGE_ROT(st); STAGE_ROT(ist);
    }

#pragma unroll
    for (int mi = 0; mi < 4; mi++)
#pragma unroll
        for (int ni = 0; ni < 4; ni++) {
            int col = n0 + wn * 32 + ni * 8 + 2 * tg;
            float2 bias = *(const float2*)(bc + col);
#pragma unroll
            for (int rr = 0; rr < 2; rr++) {
                int row = m0 + wm * 64 + mi * 16 + g + rr * 8;
                float2 v = make_float2(acc[mi][ni][rr * 2] + bias.x,
                                       acc[mi][ni][rr * 2 + 1] + bias.y);
                *(float2*)(out + (size_t)row * 512 + col) = v;
            }
        }
}

// ---------------------------------------------------------------------------
extern "C" void kernel_launch(void* const* d_in, const int* in_sizes, int n_in,
                              void* d_out, int out_size)
{
    (void)in_sizes; (void)n_in; (void)out_size;
    const float* x  = (const float*)d_in[0];
    const float* Wk = (const float*)d_in[1];
    const float* Wq = (const float*)d_in[2];
    const float* Wv = (const float*)d_in[3];
    const float* Wc = (const float*)d_in[4];
    const float* bc = (const float*)d_in[5];
    float* out = (float*)d_out;

    cudaFuncSetAttribute(proj_kernel,   cudaFuncAttributeMaxDynamicSharedMemorySize, SMEM_BYTES);
    cudaFuncSetAttribute(scores_kernel, cudaFuncAttributeMaxDynamicSharedMemorySize, SMEM_BYTES);
    cudaFuncSetAttribute(pv_kernel,     cudaFuncAttributeMaxDynamicSharedMemorySize, SMEM_BYTES);
    cudaFuncSetAttribute(final_kernel,  cudaFuncAttributeMaxDynamicSharedMemorySize, SMEM_BYTES);

    dim3 blk(256);

    cvt_kernel<<<10240, blk>>>((const float4*)x, (const float4*)Wq,
                               (const float4*)Wk, (const float4*)Wv,
                               (const float4*)Wc);
    proj_kernel<<<dim3(32, 32, 3), blk, SMEM_BYTES>>>();
    scores_kernel<<<dim3(16, 16, 16), blk, SMEM_BYTES>>>();
    softmax_kernel<<<dim3(32768), blk>>>();
    pv_kernel<<<dim3(4, 16, 16), blk, SMEM_BYTES>>>();
    final_kernel<<<dim3(4, 32), blk, SMEM_BYTES>>>(bc, out);
}